// round 11
// baseline (speedup 1.0000x reference)
#include <cuda_runtime.h>
#include <cuda_bf16.h>
#include <cstdint>

#define NMAX 100000
#define EMAX 800000
#define HDIM 128
#define NTILES_MAX ((NMAX + 63) / 64)   // 1563

// ---------------- static device scratch ------------------------------------
__device__ float g_bufA[NMAX * HDIM];
__device__ float g_bufB[NMAX * HDIM];
__device__ int   g_count[NMAX];
__device__ int   g_excl[NMAX];
__device__ int   g_rowstart[NMAX + 1];
__device__ int   g_cursor[NMAX];
__device__ int   g_col[EMAX];
__device__ int   g_bsum[128];
__device__ float g_sums[6 * 128];            // [layer][sum(128)|sumsq(128)]
__device__ float g_bnm[3 * 128];             // per-layer mean
__device__ float g_bns[3 * 128];             // per-layer rsqrt(var+eps)
__device__ __nv_bfloat16 g_Whi[3 * 16384];   // row-major [k][n] bf16 hi
__device__ __nv_bfloat16 g_Wlo[3 * 16384];   // row-major [k][n] bf16 lo
__device__ int   g_flag[3 * NTILES_MAX];     // per-layer per-tile row counters
__device__ int   g_is64;

// ---------------- helpers ---------------------------------------------------
__device__ __forceinline__ uint32_t smem_u32(const void* p) {
    uint32_t a;
    asm("{ .reg .u64 t; cvta.to.shared.u64 t, %1; cvt.u32.u64 %0, t; }" : "=r"(a) : "l"(p));
    return a;
}
__device__ __forceinline__ void ldsm4(uint32_t* r, uint32_t addr) {
    asm volatile("ldmatrix.sync.aligned.m8n8.x4.shared.b16 {%0,%1,%2,%3}, [%4];"
                 : "=r"(r[0]), "=r"(r[1]), "=r"(r[2]), "=r"(r[3]) : "r"(addr));
}
__device__ __forceinline__ void ldsm4t(uint32_t* r, uint32_t addr) {
    asm volatile("ldmatrix.sync.aligned.m8n8.x4.trans.shared.b16 {%0,%1,%2,%3}, [%4];"
                 : "=r"(r[0]), "=r"(r[1]), "=r"(r[2]), "=r"(r[3]) : "r"(addr));
}
__device__ __forceinline__ void mma16816(float* d, const uint32_t* a, const uint32_t* b) {
    asm volatile("mma.sync.aligned.m16n8k16.row.col.f32.bf16.bf16.f32 "
                 "{%0,%1,%2,%3}, {%4,%5,%6,%7}, {%8,%9}, {%0,%1,%2,%3};"
                 : "+f"(d[0]), "+f"(d[1]), "+f"(d[2]), "+f"(d[3])
                 : "r"(a[0]), "r"(a[1]), "r"(a[2]), "r"(a[3]), "r"(b[0]), "r"(b[1]));
}
__device__ __forceinline__ float4 bn_relu4(float4 v, float4 m4, float4 s4) {
    v.x = fmaxf((v.x - m4.x) * s4.x, 0.f);
    v.y = fmaxf((v.y - m4.y) * s4.y, 0.f);
    v.z = fmaxf((v.z - m4.z) * s4.z, 0.f);
    v.w = fmaxf((v.w - m4.w) * s4.w, 0.f);
    return v;
}

// ---------------- init + dtype detection -----------------------------------
__global__ void k_init(int n) {
    int i  = blockIdx.x * blockDim.x + threadIdx.x;
    int st = gridDim.x * blockDim.x;
    for (int k = i; k < n; k += st) g_count[k] = 0;
    for (int k = i; k < 6 * 128; k += st) g_sums[k] = 0.f;
    for (int k = i; k < 3 * NTILES_MAX; k += st) g_flag[k] = 0;
    if (i == 0) g_is64 = 1;
}
__global__ void k_detect(const unsigned* __restrict__ w, int nwords) {
    int i = blockIdx.x * blockDim.x + threadIdx.x;
    int idx = 2 * i + 1;
    if (i < 4096 && idx < nwords) {
        if (w[idx] != 0u) atomicExch(&g_is64, 0);
    }
}
__device__ __forceinline__ int load_idx(const void* ei, long long pos, int is64) {
    if (is64) return (int)((const long long*)ei)[pos];
    return ((const int*)ei)[pos];
}

// ---------------- CSR build ------------------------------------------------
__global__ void k_count(const void* __restrict__ ei, int E, int n) {
    int is64 = g_is64;
    int i  = blockIdx.x * blockDim.x + threadIdx.x;
    int st = gridDim.x * blockDim.x;
    for (int e = i; e < E; e += st) {
        int d = load_idx(ei, e, is64);
        if ((unsigned)d < (unsigned)n) atomicAdd(&g_count[d], 1);
    }
}
__global__ void k_scan1(int n) {
    __shared__ int s[256];
    int tid  = threadIdx.x;
    int base = blockIdx.x * 1024 + tid * 4;
    int v[4];
#pragma unroll
    for (int i = 0; i < 4; i++) v[i] = (base + i < n) ? g_count[base + i] : 0;
    int tsum = v[0] + v[1] + v[2] + v[3];
    s[tid] = tsum;
    __syncthreads();
#pragma unroll
    for (int off = 1; off < 256; off <<= 1) {
        int x = (tid >= off) ? s[tid - off] : 0;
        __syncthreads();
        s[tid] += x;
        __syncthreads();
    }
    int run = s[tid] - tsum;
#pragma unroll
    for (int i = 0; i < 4; i++) {
        if (base + i < n) g_excl[base + i] = run;
        run += v[i];
    }
    if (tid == 255) g_bsum[blockIdx.x] = s[255];
}
__global__ void k_scan2(int nb) {
    __shared__ int s[128];
    int tid = threadIdx.x;
    int v   = (tid < nb) ? g_bsum[tid] : 0;
    s[tid] = v;
    __syncthreads();
#pragma unroll
    for (int off = 1; off < 128; off <<= 1) {
        int x = (tid >= off) ? s[tid - off] : 0;
        __syncthreads();
        s[tid] += x;
        __syncthreads();
    }
    if (tid < nb) g_bsum[tid] = s[tid] - v;
}
__global__ void k_scan3(int n) {
    int i  = blockIdx.x * blockDim.x + threadIdx.x;
    int st = gridDim.x * blockDim.x;
    for (int k = i; k < n; k += st) {
        int r = g_excl[k] + g_bsum[k >> 10];
        g_rowstart[k] = r;
        g_cursor[k]   = r;
    }
    if (i == 0)
        g_rowstart[n] = g_excl[n - 1] + g_bsum[(n - 1) >> 10] + g_count[n - 1];
}
__global__ void k_scatter(const void* __restrict__ ei, int E, int n) {
    int is64 = g_is64;
    int i  = blockIdx.x * blockDim.x + threadIdx.x;
    int st = gridDim.x * blockDim.x;
    for (int e = i; e < E; e += st) {
        int d = load_idx(ei, e, is64);
        if ((unsigned)d >= (unsigned)n) continue;
        int s = load_idx(ei, (long long)E + e, is64);
        if ((unsigned)s >= (unsigned)n) s = d;
        int p = atomicAdd(&g_cursor[d], 1);
        if ((unsigned)p < (unsigned)EMAX) g_col[p] = s;
    }
}

// ---------------- weight prep: fp32 [k][n] -> row-major bf16 hi/lo ----------
__global__ void k_wprep(const float* __restrict__ W, int l) {
    int idx = blockIdx.x * blockDim.x + threadIdx.x;
    if (idx >= 16384) return;
    float v = W[idx];
    __nv_bfloat16 hi = __float2bfloat16_rn(v);
    __nv_bfloat16 lo = __float2bfloat16_rn(v - __bfloat162float(hi));
    g_Whi[l * 16384 + idx] = hi;
    g_Wlo[l * 16384 + idx] = lo;
}

// ---------------- aggregation (+BN+ReLU of prev), MLP=8, per-tile flags -----
__global__ void k_aggregate(const float* __restrict__ P, float* __restrict__ Q, int n,
                            const float* __restrict__ bnm, const float* __restrict__ bns,
                            int* __restrict__ flag) {
    int warp = (blockIdx.x * blockDim.x + threadIdx.x) >> 5;
    int lane = threadIdx.x & 31;
    if (warp >= n) return;
    bool dobn = (bnm != nullptr);
    float4 m4 = make_float4(0.f, 0.f, 0.f, 0.f);
    float4 s4 = make_float4(1.f, 1.f, 1.f, 1.f);
    if (dobn) {
        m4 = ((const float4*)bnm)[lane];
        s4 = ((const float4*)bns)[lane];
    }
    const float4* P4 = (const float4*)P;
    float4 acc = P4[(size_t)warp * 32 + lane];
    if (dobn) acc = bn_relu4(acc, m4, s4);
    int s = g_rowstart[warp];
    int t = g_rowstart[warp + 1];
    for (int p = s; p < t; p += 32) {
        int cnt = min(32, t - p);
        int j = (lane < cnt) ? g_col[p + lane] : 0;
        int q = 0;
        for (; q + 8 <= cnt; q += 8) {          // 8 independent loads in flight
            int jj[8];
#pragma unroll
            for (int u = 0; u < 8; u++) jj[u] = __shfl_sync(0xffffffffu, j, q + u);
            float4 r[8];
#pragma unroll
            for (int u = 0; u < 8; u++) r[u] = P4[(size_t)jj[u] * 32 + lane];
#pragma unroll
            for (int u = 0; u < 8; u++) {
                float4 v = dobn ? bn_relu4(r[u], m4, s4) : r[u];
                acc.x += v.x; acc.y += v.y; acc.z += v.z; acc.w += v.w;
            }
        }
        for (; q + 4 <= cnt; q += 4) {
            int j0 = __shfl_sync(0xffffffffu, j, q);
            int j1 = __shfl_sync(0xffffffffu, j, q + 1);
            int j2 = __shfl_sync(0xffffffffu, j, q + 2);
            int j3 = __shfl_sync(0xffffffffu, j, q + 3);
            float4 r0 = P4[(size_t)j0 * 32 + lane];
            float4 r1 = P4[(size_t)j1 * 32 + lane];
            float4 r2 = P4[(size_t)j2 * 32 + lane];
            float4 r3 = P4[(size_t)j3 * 32 + lane];
            if (dobn) {
                r0 = bn_relu4(r0, m4, s4); r1 = bn_relu4(r1, m4, s4);
                r2 = bn_relu4(r2, m4, s4); r3 = bn_relu4(r3, m4, s4);
            }
            acc.x += r0.x + r1.x + r2.x + r3.x;
            acc.y += r0.y + r1.y + r2.y + r3.y;
            acc.z += r0.z + r1.z + r2.z + r3.z;
            acc.w += r0.w + r1.w + r2.w + r3.w;
        }
        for (; q < cnt; q++) {
            int jj = __shfl_sync(0xffffffffu, j, q);
            float4 r = P4[(size_t)jj * 32 + lane];
            if (dobn) r = bn_relu4(r, m4, s4);
            acc.x += r.x; acc.y += r.y; acc.z += r.z; acc.w += r.w;
        }
    }
    ((float4*)Q)[(size_t)warp * 32 + lane] = acc;
    __threadfence();                       // row visible before flag bump
    if (lane == 0) atomicAdd(&flag[warp >> 6], 1);
}

// ---------------- persistent mma.sync bf16 GEMM + bias + BN stats -----------
// Spins per tile on the aggregation's row counters -> overlaps with agg.
#define PA 136
#define ATILEB (64 * PA * 2)            // 17408 B
#define WTILEB (128 * PA * 2)           // 34816 B
#define OFF_AHI 0
#define OFF_ALO ATILEB
#define OFF_WHI (2 * ATILEB)
#define OFF_WLO (2 * ATILEB + WTILEB)
#define SMEM_MMA (2 * ATILEB + 2 * WTILEB)   // 104448 B -> 2 CTAs/SM

__global__ __launch_bounds__(128) void k_gemm_mma(
    float* __restrict__ A, const __nv_bfloat16* __restrict__ Whi,
    const __nv_bfloat16* __restrict__ Wlo, const float* __restrict__ bias,
    float* __restrict__ gsum, float* __restrict__ gsq, int n, int ntiles,
    int* __restrict__ flag)
{
    extern __shared__ char sm[];
    int tid  = threadIdx.x;
    int lane = tid & 31;
    int warp = tid >> 5;

    // ---- W hi/lo tiles: load once ------------------------------------------
    for (int i = tid; i < 4096; i += 128) {
        int k = i >> 5, c4 = (i & 31) * 4;
        uint2 h = *(const uint2*)((const char*)Whi + k * 256 + c4 * 2);
        uint2 l = *(const uint2*)((const char*)Wlo + k * 256 + c4 * 2);
        *(uint2*)(sm + OFF_WHI + k * (PA * 2) + c4 * 2) = h;
        *(uint2*)(sm + OFF_WLO + k * (PA * 2) + c4 * 2) = l;
    }

    int m  = lane >> 3, ri = lane & 7;
    int rowAl = warp * 16 + (m & 1) * 8 + ri;
    uint32_t aHiB = smem_u32(sm + OFF_AHI) + rowAl * (PA * 2) + (m >> 1) * 16;
    uint32_t aLoB = smem_u32(sm + OFF_ALO) + rowAl * (PA * 2) + (m >> 1) * 16;
    int rowB = lane & 15;
    uint32_t bHiB = smem_u32(sm + OFF_WHI) + rowB * (PA * 2) + (lane >> 4) * 16;
    uint32_t bLoB = smem_u32(sm + OFF_WLO) + rowB * (PA * 2) + (lane >> 4) * 16;

    const float4* A4 = (const float4*)A;
    float* sred  = (float*)sm;
    float* sredq = (float*)sm + 512;

    for (int tile = blockIdx.x; tile < ntiles; tile += gridDim.x) {
        int r0g = tile * 64;
        // wait for the aggregation to finish this tile's rows
        if (tid == 0) {
            int need = min(64, n - r0g);
            while (atomicAdd(&flag[tile], 0) < need) __nanosleep(40);
            __threadfence();
        }
        __syncthreads();   // also guards prev-iteration sred reads

        for (int i = tid; i < 2048; i += 128) {
            int row = i >> 5, c4 = (i & 31) * 4;
            float4 v = make_float4(0.f, 0.f, 0.f, 0.f);
            if (r0g + row < n) v = A4[(size_t)(r0g + row) * 32 + (i & 31)];
            __nv_bfloat16 h0 = __float2bfloat16_rn(v.x), h1 = __float2bfloat16_rn(v.y);
            __nv_bfloat16 h2 = __float2bfloat16_rn(v.z), h3 = __float2bfloat16_rn(v.w);
            __nv_bfloat16 l0 = __float2bfloat16_rn(v.x - __bfloat162float(h0));
            __nv_bfloat16 l1 = __float2bfloat16_rn(v.y - __bfloat162float(h1));
            __nv_bfloat16 l2 = __float2bfloat16_rn(v.z - __bfloat162float(h2));
            __nv_bfloat16 l3 = __float2bfloat16_rn(v.w - __bfloat162float(h3));
            uint2 ph = make_uint2(
                (uint32_t)__bfloat16_as_ushort(h0) | ((uint32_t)__bfloat16_as_ushort(h1) << 16),
                (uint32_t)__bfloat16_as_ushort(h2) | ((uint32_t)__bfloat16_as_ushort(h3) << 16));
            uint2 pl = make_uint2(
                (uint32_t)__bfloat16_as_ushort(l0) | ((uint32_t)__bfloat16_as_ushort(l1) << 16),
                (uint32_t)__bfloat16_as_ushort(l2) | ((uint32_t)__bfloat16_as_ushort(l3) << 16));
            *(uint2*)(sm + OFF_AHI + row * (PA * 2) + c4 * 2) = ph;
            *(uint2*)(sm + OFF_ALO + row * (PA * 2) + c4 * 2) = pl;
        }
        __syncthreads();

        float acc[16][4];
#pragma unroll
        for (int t = 0; t < 16; t++)
#pragma unroll
            for (int j = 0; j < 4; j++) acc[t][j] = 0.f;

#pragma unroll
        for (int kc = 0; kc < 8; kc++) {
            uint32_t ah[4], al[4];
            ldsm4(ah, aHiB + kc * 32);
            ldsm4(al, aLoB + kc * 32);
            uint32_t kb = kc * 16 * (PA * 2);
#pragma unroll
            for (int nt = 0; nt < 8; nt++) {
                uint32_t bh[4], bl[4];
                ldsm4t(bh, bHiB + kb + nt * 32);
                ldsm4t(bl, bLoB + kb + nt * 32);
                mma16816(acc[2 * nt],     ah, bh);
                mma16816(acc[2 * nt],     al, bh);
                mma16816(acc[2 * nt],     ah, bl);
                mma16816(acc[2 * nt + 1], ah, bh + 2);
                mma16816(acc[2 * nt + 1], al, bh + 2);
                mma16816(acc[2 * nt + 1], ah, bl + 2);
            }
        }
        __syncthreads();   // A tiles dead; sred aliases them

        int lr = lane >> 2;
        int lc = lane & 3;
        int row0 = r0g + warp * 16 + lr;
        int row1 = row0 + 8;
        bool v0 = row0 < n, v1 = row1 < n;
#pragma unroll
        for (int nt = 0; nt < 16; nt++) {
            int c0 = nt * 8 + lc * 2;
            float b0v = __ldg(bias + c0), b1v = __ldg(bias + c0 + 1);
            float y00 = acc[nt][0] + b0v, y01 = acc[nt][1] + b1v;
            float y10 = acc[nt][2] + b0v, y11 = acc[nt][3] + b1v;
            if (v0) *(float2*)&A[(size_t)row0 * 128 + c0] = make_float2(y00, y01);
            if (v1) *(float2*)&A[(size_t)row1 * 128 + c0] = make_float2(y10, y11);
            float s0 = (v0 ? y00 : 0.f) + (v1 ? y10 : 0.f);
            float s1 = (v0 ? y01 : 0.f) + (v1 ? y11 : 0.f);
            float q0 = (v0 ? y00 * y00 : 0.f) + (v1 ? y10 * y10 : 0.f);
            float q1 = (v0 ? y01 * y01 : 0.f) + (v1 ? y11 * y11 : 0.f);
#pragma unroll
            for (int o = 4; o < 32; o <<= 1) {
                s0 += __shfl_xor_sync(0xffffffffu, s0, o);
                s1 += __shfl_xor_sync(0xffffffffu, s1, o);
                q0 += __shfl_xor_sync(0xffffffffu, q0, o);
                q1 += __shfl_xor_sync(0xffffffffu, q1, o);
            }
            if (lr == 0) {
                sred [warp * 128 + c0]     = s0;
                sred [warp * 128 + c0 + 1] = s1;
                sredq[warp * 128 + c0]     = q0;
                sredq[warp * 128 + c0 + 1] = q1;
            }
        }
        __syncthreads();
        if (tid < 128) {
            float s = 0.f, q = 0.f;
#pragma unroll
            for (int w = 0; w < 4; w++) {
                s += sred [w * 128 + tid];
                q += sredq[w * 128 + tid];
            }
            atomicAdd(&gsum[tid], s);
            atomicAdd(&gsq[tid], q);
        }
    }
}

// ---------------- BN finalize (per layer, tiny) -----------------------------
__global__ void k_bnfin(int l, int n) {
    int c = threadIdx.x;
    float inv_n = 1.0f / (float)n;
    float m = g_sums[l * 256 + c] * inv_n;
    float v = g_sums[l * 256 + 128 + c] * inv_n - m * m;
    g_bnm[l * 128 + c] = m;
    g_bns[l * 128 + c] = rsqrtf(v + 1e-5f);
}

// ---------------- final GEMM 128 -> 40 + bias (BN+ReLU fused on load) ------
#define SMEM40 ((128 * 132 + 128 * 40) * 4)
__global__ __launch_bounds__(128) void k_gemm40(
    const float* __restrict__ A, const float* __restrict__ W,
    const float* __restrict__ bias, float* __restrict__ out, int n,
    const float* __restrict__ bnm, const float* __restrict__ bns)
{
    extern __shared__ float smf[];
    float* As = smf;              // [128][132]
    float* Ws = smf + 128 * 132;  // [128][40]
    int tid = threadIdx.x;
    int r0  = blockIdx.x * 128;

    for (int i = tid; i < 4096; i += 128) {
        int row = i >> 5, k4 = i & 31;
        float4 v = make_float4(0.f, 0.f, 0.f, 0.f);
        if (r0 + row < n) {
            v = ((const float4*)A)[(size_t)(r0 + row) * 32 + k4];
            float4 m4 = ((const float4*)bnm)[k4];
            float4 s4 = ((const float4*)bns)[k4];
            v = bn_relu4(v, m4, s4);
        }
        float* d = &As[row * 132 + k4 * 4];
        d[0] = v.x; d[1] = v.y; d[2] = v.z; d[3] = v.w;
    }
    for (int i = tid; i < 1280; i += 128)
        ((float4*)Ws)[i] = ((const float4*)W)[i];
    __syncthreads();

    int tr = tid >> 3;   // 0..15 -> rows tr*8 .. +7
    int tc = tid & 7;    // 0..7  -> cols tc*5 .. +4
    float acc[8][5];
#pragma unroll
    for (int i = 0; i < 8; i++)
#pragma unroll
        for (int j = 0; j < 5; j++) acc[i][j] = 0.f;

    for (int k = 0; k < 128; k += 4) {
        float4 a[8];
#pragma unroll
        for (int i = 0; i < 8; i++) a[i] = *(const float4*)&As[(tr * 8 + i) * 132 + k];
#pragma unroll
        for (int kk = 0; kk < 4; kk++) {
            float b[5];
#pragma unroll
            for (int j = 0; j < 5; j++) b[j] = Ws[(k + kk) * 40 + tc * 5 + j];
#pragma unroll
            for (int i = 0; i < 8; i++) {
                float av = ((const float*)&a[i])[kk];
#pragma unroll
                for (int j = 0; j < 5; j++) acc[i][j] += av * b[j];
            }
        }
    }
    float br[5];
#pragma unroll
    for (int j = 0; j < 5; j++) br[j] = bias[tc * 5 + j];
#pragma unroll
    for (int i = 0; i < 8; i++) {
        int row = r0 + tr * 8 + i;
        if (row < n) {
#pragma unroll
            for (int j = 0; j < 5; j++)
                out[(size_t)row * 40 + tc * 5 + j] = acc[i][j] + br[j];
        }
    }
}

// ---------------- launcher -------------------------------------------------
extern "C" void kernel_launch(void* const* d_in, const int* in_sizes, int n_in,
                              void* d_out, int out_size)
{
    const float* x  = (const float*)d_in[0];
    const void*  ei = d_in[1];
    const float* W0 = (const float*)d_in[2];
    const float* b0 = (const float*)d_in[3];
    const float* W1 = (const float*)d_in[4];
    const float* b1 = (const float*)d_in[5];
    const float* W2 = (const float*)d_in[6];
    const float* b2 = (const float*)d_in[7];
    const float* Wl = (const float*)d_in[8];
    const float* bl = (const float*)d_in[9];
    float* out = (float*)d_out;

    int n = in_sizes[0] / HDIM;
    int E = in_sizes[1] / 2;

    float *bufA, *bufB, *sums, *bnm, *bns;
    __nv_bfloat16 *whi, *wlo;
    int* flags;
    cudaGetSymbolAddress((void**)&bufA,  g_bufA);
    cudaGetSymbolAddress((void**)&bufB,  g_bufB);
    cudaGetSymbolAddress((void**)&sums,  g_sums);
    cudaGetSymbolAddress((void**)&bnm,   g_bnm);
    cudaGetSymbolAddress((void**)&bns,   g_bns);
    cudaGetSymbolAddress((void**)&whi,   g_Whi);
    cudaGetSymbolAddress((void**)&wlo,   g_Wlo);
    cudaGetSymbolAddress((void**)&flags, g_flag);

    cudaFuncSetAttribute(k_gemm_mma, cudaFuncAttributeMaxDynamicSharedMemorySize, SMEM_MMA);
    cudaFuncSetAttribute(k_gemm40,   cudaFuncAttributeMaxDynamicSharedMemorySize, SMEM40);

    // side stream + events for agg/gemm overlap (created once; host objects)
    static cudaStream_t s2 = nullptr;
    static cudaEvent_t  evF = nullptr, evJ = nullptr;
    if (s2 == nullptr) {
        cudaStreamCreateWithFlags(&s2, cudaStreamNonBlocking);
        cudaEventCreateWithFlags(&evF, cudaEventDisableTiming);
        cudaEventCreateWithFlags(&evJ, cudaEventDisableTiming);
    }

    int nb = (n + 1023) >> 10;

    k_init<<<256, 256>>>(n);
    // fork: weight prep + layer-0 GEMM run on s2 while CSR builds on main
    cudaEventRecord(evF, 0);
    cudaStreamWaitEvent(s2, evF, 0);
    k_wprep<<<64, 256, 0, s2>>>(W0, 0);
    k_wprep<<<64, 256, 0, s2>>>(W1, 1);
    k_wprep<<<64, 256, 0, s2>>>(W2, 2);

    k_detect<<<16, 256>>>((const unsigned*)ei, in_sizes[1]);
    k_count<<<(E + 255) / 256, 256>>>(ei, E, n);
    k_scan1<<<nb, 256>>>(n);
    k_scan2<<<1, 128>>>(nb);
    k_scan3<<<(n + 255) / 256, 256>>>(n);
    k_scatter<<<(E + 255) / 256, 256>>>(ei, E, n);

    const float* bs_[3] = { b0, b1, b2 };
    float* bufs[2] = { bufA, bufB };
    const float* P = x;
    int ntiles = (n + 63) / 64;
    int ggrid  = ntiles < 296 ? ntiles : 296;   // 2 CTAs/SM persistent
    for (int l = 0; l < 3; l++) {
        float* Q = bufs[l & 1];
        const float* pm  = (l == 0) ? nullptr : bnm + (l - 1) * 128;
        const float* psd = (l == 0) ? nullptr : bns + (l - 1) * 128;
        if (l > 0) {                       // gemm_l must see bnfin_{l-1} etc
            cudaEventRecord(evF, 0);
            cudaStreamWaitEvent(s2, evF, 0);
        }
        // consumer first (spins on flags), producer second -> they overlap
        k_gemm_mma<<<ggrid, 128, SMEM_MMA, s2>>>(Q, whi + l * 16384, wlo + l * 16384,
                                                 bs_[l], sums + l * 256,
                                                 sums + l * 256 + 128, n, ntiles,
                                                 flags + l * NTILES_MAX);
        k_aggregate<<<(n * 32 + 255) / 256, 256>>>(P, Q, n, pm, psd,
                                                   flags + l * NTILES_MAX);
        cudaEventRecord(evJ, s2);
        cudaStreamWaitEvent(0, evJ, 0);    // join before BN finalize
        k_bnfin<<<1, 128>>>(l, n);
        P = Q;
    }
    k_gemm40<<<(n + 127) / 128, 128, SMEM40>>>(P, Wl, bl, out, n,
                                               bnm + 2 * 128, bns + 2 * 128);
}

// round 12
// speedup vs baseline: 1.3384x; 1.3384x over previous
#include <cuda_runtime.h>
#include <cuda_bf16.h>
#include <cstdint>

#define NMAX 100000
#define EMAX 800000
#define HDIM 128

// ---------------- static device scratch ------------------------------------
__device__ float g_bufA[NMAX * HDIM];
__device__ float g_bufB[NMAX * HDIM];
__device__ int   g_count[NMAX];
__device__ int   g_excl[NMAX];
__device__ int   g_rowstart[NMAX + 1];
__device__ int   g_cursor[NMAX];
__device__ int   g_col[EMAX];
__device__ int   g_bsum[128];
__device__ float g_sums[6 * 128];            // [layer][sum(128)|sumsq(128)]
__device__ float g_bnm[3 * 128];             // per-layer mean
__device__ float g_bns[3 * 128];             // per-layer rsqrt(var+eps)
__device__ __nv_bfloat16 g_Whi[3 * 16384];   // row-major [k][n] bf16 hi
__device__ __nv_bfloat16 g_Wlo[3 * 16384];   // row-major [k][n] bf16 lo
__device__ int   g_done[3];                  // per-layer GEMM completion ctr
__device__ int   g_is64;

// ---------------- helpers ---------------------------------------------------
__device__ __forceinline__ uint32_t smem_u32(const void* p) {
    uint32_t a;
    asm("{ .reg .u64 t; cvta.to.shared.u64 t, %1; cvt.u32.u64 %0, t; }" : "=r"(a) : "l"(p));
    return a;
}
__device__ __forceinline__ void ldsm4(uint32_t* r, uint32_t addr) {
    asm volatile("ldmatrix.sync.aligned.m8n8.x4.shared.b16 {%0,%1,%2,%3}, [%4];"
                 : "=r"(r[0]), "=r"(r[1]), "=r"(r[2]), "=r"(r[3]) : "r"(addr));
}
__device__ __forceinline__ void ldsm4t(uint32_t* r, uint32_t addr) {
    asm volatile("ldmatrix.sync.aligned.m8n8.x4.trans.shared.b16 {%0,%1,%2,%3}, [%4];"
                 : "=r"(r[0]), "=r"(r[1]), "=r"(r[2]), "=r"(r[3]) : "r"(addr));
}
__device__ __forceinline__ void mma16816(float* d, const uint32_t* a, const uint32_t* b) {
    asm volatile("mma.sync.aligned.m16n8k16.row.col.f32.bf16.bf16.f32 "
                 "{%0,%1,%2,%3}, {%4,%5,%6,%7}, {%8,%9}, {%0,%1,%2,%3};"
                 : "+f"(d[0]), "+f"(d[1]), "+f"(d[2]), "+f"(d[3])
                 : "r"(a[0]), "r"(a[1]), "r"(a[2]), "r"(a[3]), "r"(b[0]), "r"(b[1]));
}
__device__ __forceinline__ float4 bn_relu4(float4 v, float4 m4, float4 s4) {
    v.x = fmaxf((v.x - m4.x) * s4.x, 0.f);
    v.y = fmaxf((v.y - m4.y) * s4.y, 0.f);
    v.z = fmaxf((v.z - m4.z) * s4.z, 0.f);
    v.w = fmaxf((v.w - m4.w) * s4.w, 0.f);
    return v;
}

// ---------------- init + dtype detection -----------------------------------
__global__ void k_init(int n) {
    int i  = blockIdx.x * blockDim.x + threadIdx.x;
    int st = gridDim.x * blockDim.x;
    for (int k = i; k < n; k += st) g_count[k] = 0;
    for (int k = i; k < 6 * 128; k += st) g_sums[k] = 0.f;
    if (i == 0) {
        g_is64 = 1;
        g_done[0] = g_done[1] = g_done[2] = 0;
    }
}
__global__ void k_detect(const unsigned* __restrict__ w, int nwords) {
    int i = blockIdx.x * blockDim.x + threadIdx.x;
    int idx = 2 * i + 1;
    if (i < 4096 && idx < nwords) {
        if (w[idx] != 0u) atomicExch(&g_is64, 0);
    }
}
__device__ __forceinline__ int load_idx(const void* ei, long long pos, int is64) {
    if (is64) return (int)((const long long*)ei)[pos];
    return ((const int*)ei)[pos];
}

// ---------------- CSR build ------------------------------------------------
__global__ void k_count(const void* __restrict__ ei, int E, int n) {
    int is64 = g_is64;
    int i  = blockIdx.x * blockDim.x + threadIdx.x;
    int st = gridDim.x * blockDim.x;
    for (int e = i; e < E; e += st) {
        int d = load_idx(ei, e, is64);
        if ((unsigned)d < (unsigned)n) atomicAdd(&g_count[d], 1);
    }
}
__global__ void k_scan1(int n) {
    __shared__ int s[256];
    int tid  = threadIdx.x;
    int base = blockIdx.x * 1024 + tid * 4;
    int v[4];
#pragma unroll
    for (int i = 0; i < 4; i++) v[i] = (base + i < n) ? g_count[base + i] : 0;
    int tsum = v[0] + v[1] + v[2] + v[3];
    s[tid] = tsum;
    __syncthreads();
#pragma unroll
    for (int off = 1; off < 256; off <<= 1) {
        int x = (tid >= off) ? s[tid - off] : 0;
        __syncthreads();
        s[tid] += x;
        __syncthreads();
    }
    int run = s[tid] - tsum;
#pragma unroll
    for (int i = 0; i < 4; i++) {
        if (base + i < n) g_excl[base + i] = run;
        run += v[i];
    }
    if (tid == 255) g_bsum[blockIdx.x] = s[255];
}
__global__ void k_scan2(int nb) {
    __shared__ int s[128];
    int tid = threadIdx.x;
    int v   = (tid < nb) ? g_bsum[tid] : 0;
    s[tid] = v;
    __syncthreads();
#pragma unroll
    for (int off = 1; off < 128; off <<= 1) {
        int x = (tid >= off) ? s[tid - off] : 0;
        __syncthreads();
        s[tid] += x;
        __syncthreads();
    }
    if (tid < nb) g_bsum[tid] = s[tid] - v;
}
__global__ void k_scan3(int n) {
    int i  = blockIdx.x * blockDim.x + threadIdx.x;
    int st = gridDim.x * blockDim.x;
    for (int k = i; k < n; k += st) {
        int r = g_excl[k] + g_bsum[k >> 10];
        g_rowstart[k] = r;
        g_cursor[k]   = r;
    }
    if (i == 0)
        g_rowstart[n] = g_excl[n - 1] + g_bsum[(n - 1) >> 10] + g_count[n - 1];
}
__global__ void k_scatter(const void* __restrict__ ei, int E, int n) {
    int is64 = g_is64;
    int i  = blockIdx.x * blockDim.x + threadIdx.x;
    int st = gridDim.x * blockDim.x;
    for (int e = i; e < E; e += st) {
        int d = load_idx(ei, e, is64);
        if ((unsigned)d >= (unsigned)n) continue;
        int s = load_idx(ei, (long long)E + e, is64);
        if ((unsigned)s >= (unsigned)n) s = d;
        int p = atomicAdd(&g_cursor[d], 1);
        if ((unsigned)p < (unsigned)EMAX) g_col[p] = s;
    }
}

// ---------------- weight prep: fp32 [k][n] -> row-major bf16 hi/lo ----------
__global__ void k_wprep(const float* __restrict__ W, int l) {
    int idx = blockIdx.x * blockDim.x + threadIdx.x;
    if (idx >= 16384) return;
    float v = W[idx];
    __nv_bfloat16 hi = __float2bfloat16_rn(v);
    __nv_bfloat16 lo = __float2bfloat16_rn(v - __bfloat162float(hi));
    g_Whi[l * 16384 + idx] = hi;
    g_Wlo[l * 16384 + idx] = lo;
}

// ---------------- aggregation (+ fused BN+ReLU of prev layer), MLP=8 -------
__global__ void k_aggregate(const float* __restrict__ P, float* __restrict__ Q, int n,
                            const float* __restrict__ bnm, const float* __restrict__ bns) {
    int warp = (blockIdx.x * blockDim.x + threadIdx.x) >> 5;
    int lane = threadIdx.x & 31;
    if (warp >= n) return;
    bool dobn = (bnm != nullptr);
    float4 m4 = make_float4(0.f, 0.f, 0.f, 0.f);
    float4 s4 = make_float4(1.f, 1.f, 1.f, 1.f);
    if (dobn) {
        m4 = ((const float4*)bnm)[lane];
        s4 = ((const float4*)bns)[lane];
    }
    const float4* P4 = (const float4*)P;
    float4 acc = P4[(size_t)warp * 32 + lane];
    if (dobn) acc = bn_relu4(acc, m4, s4);
    int s = g_rowstart[warp];
    int t = g_rowstart[warp + 1];
    for (int p = s; p < t; p += 32) {
        int cnt = min(32, t - p);
        int j = (lane < cnt) ? g_col[p + lane] : 0;
        int q = 0;
        for (; q + 8 <= cnt; q += 8) {          // 8 independent loads in flight
            int jj[8];
#pragma unroll
            for (int u = 0; u < 8; u++) jj[u] = __shfl_sync(0xffffffffu, j, q + u);
            float4 r[8];
#pragma unroll
            for (int u = 0; u < 8; u++) r[u] = P4[(size_t)jj[u] * 32 + lane];
#pragma unroll
            for (int u = 0; u < 8; u++) {
                float4 v = dobn ? bn_relu4(r[u], m4, s4) : r[u];
                acc.x += v.x; acc.y += v.y; acc.z += v.z; acc.w += v.w;
            }
        }
        for (; q + 4 <= cnt; q += 4) {
            int j0 = __shfl_sync(0xffffffffu, j, q);
            int j1 = __shfl_sync(0xffffffffu, j, q + 1);
            int j2 = __shfl_sync(0xffffffffu, j, q + 2);
            int j3 = __shfl_sync(0xffffffffu, j, q + 3);
            float4 r0 = P4[(size_t)j0 * 32 + lane];
            float4 r1 = P4[(size_t)j1 * 32 + lane];
            float4 r2 = P4[(size_t)j2 * 32 + lane];
            float4 r3 = P4[(size_t)j3 * 32 + lane];
            if (dobn) {
                r0 = bn_relu4(r0, m4, s4); r1 = bn_relu4(r1, m4, s4);
                r2 = bn_relu4(r2, m4, s4); r3 = bn_relu4(r3, m4, s4);
            }
            acc.x += r0.x + r1.x + r2.x + r3.x;
            acc.y += r0.y + r1.y + r2.y + r3.y;
            acc.z += r0.z + r1.z + r2.z + r3.z;
            acc.w += r0.w + r1.w + r2.w + r3.w;
        }
        for (; q < cnt; q++) {
            int jj = __shfl_sync(0xffffffffu, j, q);
            float4 r = P4[(size_t)jj * 32 + lane];
            if (dobn) r = bn_relu4(r, m4, s4);
            acc.x += r.x; acc.y += r.y; acc.z += r.z; acc.w += r.w;
        }
    }
    ((float4*)Q)[(size_t)warp * 32 + lane] = acc;
}

// ---------------- persistent mma.sync bf16 GEMM + bias + BN stats -----------
// Last CTA to finish also computes bnm/bns (folds k_bnfin into the epilogue).
#define PA 136
#define ATILEB (64 * PA * 2)            // 17408 B
#define WTILEB (128 * PA * 2)           // 34816 B
#define OFF_AHI 0
#define OFF_ALO ATILEB
#define OFF_WHI (2 * ATILEB)
#define OFF_WLO (2 * ATILEB + WTILEB)
#define SMEM_MMA (2 * ATILEB + 2 * WTILEB)   // 104448 B -> 2 CTAs/SM

__global__ __launch_bounds__(128) void k_gemm_mma(
    float* __restrict__ A, const __nv_bfloat16* __restrict__ Whi,
    const __nv_bfloat16* __restrict__ Wlo, const float* __restrict__ bias,
    float* __restrict__ gsum, float* __restrict__ gsq, int n, int ntiles,
    float* __restrict__ bnm_out, float* __restrict__ bns_out,
    int* __restrict__ done)
{
    extern __shared__ char sm[];
    __shared__ int s_last;
    int tid  = threadIdx.x;
    int lane = tid & 31;
    int warp = tid >> 5;

    // ---- W hi/lo tiles: load once ------------------------------------------
    for (int i = tid; i < 4096; i += 128) {
        int k = i >> 5, c4 = (i & 31) * 4;
        uint2 h = *(const uint2*)((const char*)Whi + k * 256 + c4 * 2);
        uint2 l = *(const uint2*)((const char*)Wlo + k * 256 + c4 * 2);
        *(uint2*)(sm + OFF_WHI + k * (PA * 2) + c4 * 2) = h;
        *(uint2*)(sm + OFF_WLO + k * (PA * 2) + c4 * 2) = l;
    }

    int m  = lane >> 3, ri = lane & 7;
    int rowAl = warp * 16 + (m & 1) * 8 + ri;
    uint32_t aHiB = smem_u32(sm + OFF_AHI) + rowAl * (PA * 2) + (m >> 1) * 16;
    uint32_t aLoB = smem_u32(sm + OFF_ALO) + rowAl * (PA * 2) + (m >> 1) * 16;
    int rowB = lane & 15;
    uint32_t bHiB = smem_u32(sm + OFF_WHI) + rowB * (PA * 2) + (lane >> 4) * 16;
    uint32_t bLoB = smem_u32(sm + OFF_WLO) + rowB * (PA * 2) + (lane >> 4) * 16;

    const float4* A4 = (const float4*)A;
    float* sred  = (float*)sm;
    float* sredq = (float*)sm + 512;

    for (int tile = blockIdx.x; tile < ntiles; tile += gridDim.x) {
        int r0g = tile * 64;
        __syncthreads();   // previous iteration's stats reads done

        for (int i = tid; i < 2048; i += 128) {
            int row = i >> 5, c4 = (i & 31) * 4;
            float4 v = make_float4(0.f, 0.f, 0.f, 0.f);
            if (r0g + row < n) v = A4[(size_t)(r0g + row) * 32 + (i & 31)];
            __nv_bfloat16 h0 = __float2bfloat16_rn(v.x), h1 = __float2bfloat16_rn(v.y);
            __nv_bfloat16 h2 = __float2bfloat16_rn(v.z), h3 = __float2bfloat16_rn(v.w);
            __nv_bfloat16 l0 = __float2bfloat16_rn(v.x - __bfloat162float(h0));
            __nv_bfloat16 l1 = __float2bfloat16_rn(v.y - __bfloat162float(h1));
            __nv_bfloat16 l2 = __float2bfloat16_rn(v.z - __bfloat162float(h2));
            __nv_bfloat16 l3 = __float2bfloat16_rn(v.w - __bfloat162float(h3));
            uint2 ph = make_uint2(
                (uint32_t)__bfloat16_as_ushort(h0) | ((uint32_t)__bfloat16_as_ushort(h1) << 16),
                (uint32_t)__bfloat16_as_ushort(h2) | ((uint32_t)__bfloat16_as_ushort(h3) << 16));
            uint2 pl = make_uint2(
                (uint32_t)__bfloat16_as_ushort(l0) | ((uint32_t)__bfloat16_as_ushort(l1) << 16),
                (uint32_t)__bfloat16_as_ushort(l2) | ((uint32_t)__bfloat16_as_ushort(l3) << 16));
            *(uint2*)(sm + OFF_AHI + row * (PA * 2) + c4 * 2) = ph;
            *(uint2*)(sm + OFF_ALO + row * (PA * 2) + c4 * 2) = pl;
        }
        __syncthreads();

        float acc[16][4];
#pragma unroll
        for (int t = 0; t < 16; t++)
#pragma unroll
            for (int j = 0; j < 4; j++) acc[t][j] = 0.f;

#pragma unroll
        for (int kc = 0; kc < 8; kc++) {
            uint32_t ah[4], al[4];
            ldsm4(ah, aHiB + kc * 32);
            ldsm4(al, aLoB + kc * 32);
            uint32_t kb = kc * 16 * (PA * 2);
#pragma unroll
            for (int nt = 0; nt < 8; nt++) {
                uint32_t bh[4], bl[4];
                ldsm4t(bh, bHiB + kb + nt * 32);
                ldsm4t(bl, bLoB + kb + nt * 32);
                mma16816(acc[2 * nt],     ah, bh);
                mma16816(acc[2 * nt],     al, bh);
                mma16816(acc[2 * nt],     ah, bl);
                mma16816(acc[2 * nt + 1], ah, bh + 2);
                mma16816(acc[2 * nt + 1], al, bh + 2);
                mma16816(acc[2 * nt + 1], ah, bl + 2);
            }
        }
        __syncthreads();   // A tiles dead; sred aliases them

        int lr = lane >> 2;
        int lc = lane & 3;
        int row0 = r0g + warp * 16 + lr;
        int row1 = row0 + 8;
        bool v0 = row0 < n, v1 = row1 < n;
#pragma unroll
        for (int nt = 0; nt < 16; nt++) {
            int c0 = nt * 8 + lc * 2;
            float b0v = __ldg(bias + c0), b1v = __ldg(bias + c0 + 1);
            float y00 = acc[nt][0] + b0v, y01 = acc[nt][1] + b1v;
            float y10 = acc[nt][2] + b0v, y11 = acc[nt][3] + b1v;
            if (v0) *(float2*)&A[(size_t)row0 * 128 + c0] = make_float2(y00, y01);
            if (v1) *(float2*)&A[(size_t)row1 * 128 + c0] = make_float2(y10, y11);
            float s0 = (v0 ? y00 : 0.f) + (v1 ? y10 : 0.f);
            float s1 = (v0 ? y01 : 0.f) + (v1 ? y11 : 0.f);
            float q0 = (v0 ? y00 * y00 : 0.f) + (v1 ? y10 * y10 : 0.f);
            float q1 = (v0 ? y01 * y01 : 0.f) + (v1 ? y11 * y11 : 0.f);
#pragma unroll
            for (int o = 4; o < 32; o <<= 1) {
                s0 += __shfl_xor_sync(0xffffffffu, s0, o);
                s1 += __shfl_xor_sync(0xffffffffu, s1, o);
                q0 += __shfl_xor_sync(0xffffffffu, q0, o);
                q1 += __shfl_xor_sync(0xffffffffu, q1, o);
            }
            if (lr == 0) {
                sred [warp * 128 + c0]     = s0;
                sred [warp * 128 + c0 + 1] = s1;
                sredq[warp * 128 + c0]     = q0;
                sredq[warp * 128 + c0 + 1] = q1;
            }
        }
        __syncthreads();
        if (tid < 128) {
            float s = 0.f, q = 0.f;
#pragma unroll
            for (int w = 0; w < 4; w++) {
                s += sred [w * 128 + tid];
                q += sredq[w * 128 + tid];
            }
            atomicAdd(&gsum[tid], s);
            atomicAdd(&gsq[tid], q);
        }
    }

    // ---- fold BN finalize into the last CTA ---------------------------------
    __syncthreads();
    if (tid == 0) {
        __threadfence();                      // make our gsum/gsq atomics visible
        int v = atomicAdd(done, 1);
        s_last = (v == gridDim.x - 1) ? 1 : 0;
    }
    __syncthreads();
    if (s_last) {
        __threadfence();                      // see all CTAs' atomics
        if (tid < 128) {
            float inv_n = 1.0f / (float)n;
            float mval = gsum[tid] * inv_n;
            float vvar = gsq[tid] * inv_n - mval * mval;
            bnm_out[tid] = mval;
            bns_out[tid] = rsqrtf(vvar + 1e-5f);
        }
    }
}

// ---------------- final GEMM 128 -> 40 + bias (BN+ReLU fused on load) ------
#define SMEM40 ((128 * 132 + 128 * 40) * 4)
__global__ __launch_bounds__(128) void k_gemm40(
    const float* __restrict__ A, const float* __restrict__ W,
    const float* __restrict__ bias, float* __restrict__ out, int n,
    const float* __restrict__ bnm, const float* __restrict__ bns)
{
    extern __shared__ float smf[];
    float* As = smf;              // [128][132]
    float* Ws = smf + 128 * 132;  // [128][40]
    int tid = threadIdx.x;
    int r0  = blockIdx.x * 128;

    for (int i = tid; i < 4096; i += 128) {
        int row = i >> 5, k4 = i & 31;
        float4 v = make_float4(0.f, 0.f, 0.f, 0.f);
        if (r0 + row < n) {
            v = ((const float4*)A)[(size_t)(r0 + row) * 32 + k4];
            float4 m4 = ((const float4*)bnm)[k4];
            float4 s4 = ((const float4*)bns)[k4];
            v = bn_relu4(v, m4, s4);
        }
        float* d = &As[row * 132 + k4 * 4];
        d[0] = v.x; d[1] = v.y; d[2] = v.z; d[3] = v.w;
    }
    for (int i = tid; i < 1280; i += 128)
        ((float4*)Ws)[i] = ((const float4*)W)[i];
    __syncthreads();

    int tr = tid >> 3;   // 0..15 -> rows tr*8 .. +7
    int tc = tid & 7;    // 0..7  -> cols tc*5 .. +4
    float acc[8][5];
#pragma unroll
    for (int i = 0; i < 8; i++)
#pragma unroll
        for (int j = 0; j < 5; j++) acc[i][j] = 0.f;

    for (int k = 0; k < 128; k += 4) {
        float4 a[8];
#pragma unroll
        for (int i = 0; i < 8; i++) a[i] = *(const float4*)&As[(tr * 8 + i) * 132 + k];
#pragma unroll
        for (int kk = 0; kk < 4; kk++) {
            float b[5];
#pragma unroll
            for (int j = 0; j < 5; j++) b[j] = Ws[(k + kk) * 40 + tc * 5 + j];
#pragma unroll
            for (int i = 0; i < 8; i++) {
                float av = ((const float*)&a[i])[kk];
#pragma unroll
                for (int j = 0; j < 5; j++) acc[i][j] += av * b[j];
            }
        }
    }
    float br[5];
#pragma unroll
    for (int j = 0; j < 5; j++) br[j] = bias[tc * 5 + j];
#pragma unroll
    for (int i = 0; i < 8; i++) {
        int row = r0 + tr * 8 + i;
        if (row < n) {
#pragma unroll
            for (int j = 0; j < 5; j++)
                out[(size_t)row * 40 + tc * 5 + j] = acc[i][j] + br[j];
        }
    }
}

// ---------------- launcher -------------------------------------------------
extern "C" void kernel_launch(void* const* d_in, const int* in_sizes, int n_in,
                              void* d_out, int out_size)
{
    const float* x  = (const float*)d_in[0];
    const void*  ei = d_in[1];
    const float* W0 = (const float*)d_in[2];
    const float* b0 = (const float*)d_in[3];
    const float* W1 = (const float*)d_in[4];
    const float* b1 = (const float*)d_in[5];
    const float* W2 = (const float*)d_in[6];
    const float* b2 = (const float*)d_in[7];
    const float* Wl = (const float*)d_in[8];
    const float* bl = (const float*)d_in[9];
    float* out = (float*)d_out;

    int n = in_sizes[0] / HDIM;
    int E = in_sizes[1] / 2;

    float *bufA, *bufB, *sums, *bnm, *bns;
    __nv_bfloat16 *whi, *wlo;
    int* done;
    cudaGetSymbolAddress((void**)&bufA, g_bufA);
    cudaGetSymbolAddress((void**)&bufB, g_bufB);
    cudaGetSymbolAddress((void**)&sums, g_sums);
    cudaGetSymbolAddress((void**)&bnm,  g_bnm);
    cudaGetSymbolAddress((void**)&bns,  g_bns);
    cudaGetSymbolAddress((void**)&whi,  g_Whi);
    cudaGetSymbolAddress((void**)&wlo,  g_Wlo);
    cudaGetSymbolAddress((void**)&done, g_done);

    cudaFuncSetAttribute(k_gemm_mma, cudaFuncAttributeMaxDynamicSharedMemorySize, SMEM_MMA);
    cudaFuncSetAttribute(k_gemm40,   cudaFuncAttributeMaxDynamicSharedMemorySize, SMEM40);

    // side stream for weight-prep overlap with CSR build (host objects only)
    static cudaStream_t s2 = nullptr;
    static cudaEvent_t  evF = nullptr, evW = nullptr;
    if (s2 == nullptr) {
        cudaStreamCreateWithFlags(&s2, cudaStreamNonBlocking);
        cudaEventCreateWithFlags(&evF, cudaEventDisableTiming);
        cudaEventCreateWithFlags(&evW, cudaEventDisableTiming);
    }

    int nb = (n + 1023) >> 10;

    k_init<<<256, 256>>>(n);
    // fork: weight prep on s2 overlaps the CSR build on the main stream
    cudaEventRecord(evF, 0);
    cudaStreamWaitEvent(s2, evF, 0);
    k_wprep<<<64, 256, 0, s2>>>(W0, 0);
    k_wprep<<<64, 256, 0, s2>>>(W1, 1);
    k_wprep<<<64, 256, 0, s2>>>(W2, 2);
    cudaEventRecord(evW, s2);

    k_detect<<<16, 256>>>((const unsigned*)ei, in_sizes[1]);
    k_count<<<(E + 255) / 256, 256>>>(ei, E, n);
    k_scan1<<<nb, 256>>>(n);
    k_scan2<<<1, 128>>>(nb);
    k_scan3<<<(n + 255) / 256, 256>>>(n);
    k_scatter<<<(E + 255) / 256, 256>>>(ei, E, n);
    cudaStreamWaitEvent(0, evW, 0);        // join: GEMMs need prepped weights

    const float* bs_[3] = { b0, b1, b2 };
    float* bufs[2] = { bufA, bufB };
    const float* P = x;
    int ntiles = (n + 63) / 64;
    int ggrid  = ntiles < 296 ? ntiles : 296;   // 2 CTAs/SM persistent
    for (int l = 0; l < 3; l++) {
        float* Q = bufs[l & 1];
        const float* pm  = (l == 0) ? nullptr : bnm + (l - 1) * 128;
        const float* psd = (l == 0) ? nullptr : bns + (l - 1) * 128;
        k_aggregate<<<(n * 32 + 255) / 256, 256>>>(P, Q, n, pm, psd);
        k_gemm_mma<<<ggrid, 128, SMEM_MMA>>>(Q, whi + l * 16384, wlo + l * 16384,
                                             bs_[l], sums + l * 256,
                                             sums + l * 256 + 128, n, ntiles,
                                             bnm + l * 128, bns + l * 128,
                                             done + l);
        P = Q;
    }
    k_gemm40<<<(n + 127) / 128, 128, SMEM40>>>(P, Wl, bl, out, n,
                                               bnm + 2 * 128, bns + 2 * 128);
}

// round 13
// speedup vs baseline: 1.3932x; 1.0410x over previous
#include <cuda_runtime.h>
#include <cuda_bf16.h>
#include <cstdint>

#define NMAX 100000
#define EMAX 800000
#define HDIM 128

// ---------------- static device scratch ------------------------------------
__device__ float g_bufA[NMAX * HDIM];
__device__ float g_bufB[NMAX * HDIM];
__device__ int   g_count[NMAX];
__device__ int   g_excl[NMAX];
__device__ int   g_rowstart[NMAX + 1];
__device__ int   g_cursor[NMAX];
__device__ int   g_col[EMAX];
__device__ int   g_bsum[128];
__device__ float g_sums[6 * 128];            // [layer][sum(128)|sumsq(128)]
__device__ float g_bnm[3 * 128];             // per-layer mean
__device__ float g_bns[3 * 128];             // per-layer rsqrt(var+eps)
__device__ __nv_bfloat16 g_Whi[3 * 16384];   // row-major [k][n] bf16 hi
__device__ __nv_bfloat16 g_Wlo[3 * 16384];   // row-major [k][n] bf16 lo
__device__ __nv_bfloat16 g_W40hi[128 * 48];  // final layer, padded to 48 cols
__device__ __nv_bfloat16 g_W40lo[128 * 48];
__device__ int   g_done[3];                  // per-layer GEMM completion ctr
__device__ int   g_is64;

// ---------------- helpers ---------------------------------------------------
__device__ __forceinline__ uint32_t smem_u32(const void* p) {
    uint32_t a;
    asm("{ .reg .u64 t; cvta.to.shared.u64 t, %1; cvt.u32.u64 %0, t; }" : "=r"(a) : "l"(p));
    return a;
}
__device__ __forceinline__ void ldsm4(uint32_t* r, uint32_t addr) {
    asm volatile("ldmatrix.sync.aligned.m8n8.x4.shared.b16 {%0,%1,%2,%3}, [%4];"
                 : "=r"(r[0]), "=r"(r[1]), "=r"(r[2]), "=r"(r[3]) : "r"(addr));
}
__device__ __forceinline__ void ldsm4t(uint32_t* r, uint32_t addr) {
    asm volatile("ldmatrix.sync.aligned.m8n8.x4.trans.shared.b16 {%0,%1,%2,%3}, [%4];"
                 : "=r"(r[0]), "=r"(r[1]), "=r"(r[2]), "=r"(r[3]) : "r"(addr));
}
__device__ __forceinline__ void mma16816(float* d, const uint32_t* a, const uint32_t* b) {
    asm volatile("mma.sync.aligned.m16n8k16.row.col.f32.bf16.bf16.f32 "
                 "{%0,%1,%2,%3}, {%4,%5,%6,%7}, {%8,%9}, {%0,%1,%2,%3};"
                 : "+f"(d[0]), "+f"(d[1]), "+f"(d[2]), "+f"(d[3])
                 : "r"(a[0]), "r"(a[1]), "r"(a[2]), "r"(a[3]), "r"(b[0]), "r"(b[1]));
}
__device__ __forceinline__ float4 bn_relu4(float4 v, float4 m4, float4 s4) {
    v.x = fmaxf((v.x - m4.x) * s4.x, 0.f);
    v.y = fmaxf((v.y - m4.y) * s4.y, 0.f);
    v.z = fmaxf((v.z - m4.z) * s4.z, 0.f);
    v.w = fmaxf((v.w - m4.w) * s4.w, 0.f);
    return v;
}

// ---------------- init + dtype detection -----------------------------------
__global__ void k_init(int n) {
    int i  = blockIdx.x * blockDim.x + threadIdx.x;
    int st = gridDim.x * blockDim.x;
    for (int k = i; k < n; k += st) g_count[k] = 0;
    for (int k = i; k < 6 * 128; k += st) g_sums[k] = 0.f;
    if (i == 0) {
        g_is64 = 1;
        g_done[0] = g_done[1] = g_done[2] = 0;
    }
}
__global__ void k_detect(const unsigned* __restrict__ w, int nwords) {
    int i = blockIdx.x * blockDim.x + threadIdx.x;
    int idx = 2 * i + 1;
    if (i < 4096 && idx < nwords) {
        if (w[idx] != 0u) atomicExch(&g_is64, 0);
    }
}
__device__ __forceinline__ int load_idx(const void* ei, long long pos, int is64) {
    if (is64) return (int)((const long long*)ei)[pos];
    return ((const int*)ei)[pos];
}

// ---------------- CSR build ------------------------------------------------
__global__ void k_count(const void* __restrict__ ei, int E, int n) {
    int is64 = g_is64;
    int i  = blockIdx.x * blockDim.x + threadIdx.x;
    int st = gridDim.x * blockDim.x;
    for (int e = i; e < E; e += st) {
        int d = load_idx(ei, e, is64);
        if ((unsigned)d < (unsigned)n) atomicAdd(&g_count[d], 1);
    }
}
__global__ void k_scan1(int n) {
    __shared__ int s[256];
    int tid  = threadIdx.x;
    int base = blockIdx.x * 1024 + tid * 4;
    int v[4];
#pragma unroll
    for (int i = 0; i < 4; i++) v[i] = (base + i < n) ? g_count[base + i] : 0;
    int tsum = v[0] + v[1] + v[2] + v[3];
    s[tid] = tsum;
    __syncthreads();
#pragma unroll
    for (int off = 1; off < 256; off <<= 1) {
        int x = (tid >= off) ? s[tid - off] : 0;
        __syncthreads();
        s[tid] += x;
        __syncthreads();
    }
    int run = s[tid] - tsum;
#pragma unroll
    for (int i = 0; i < 4; i++) {
        if (base + i < n) g_excl[base + i] = run;
        run += v[i];
    }
    if (tid == 255) g_bsum[blockIdx.x] = s[255];
}
__global__ void k_scan2(int nb) {
    __shared__ int s[128];
    int tid = threadIdx.x;
    int v   = (tid < nb) ? g_bsum[tid] : 0;
    s[tid] = v;
    __syncthreads();
#pragma unroll
    for (int off = 1; off < 128; off <<= 1) {
        int x = (tid >= off) ? s[tid - off] : 0;
        __syncthreads();
        s[tid] += x;
        __syncthreads();
    }
    if (tid < nb) g_bsum[tid] = s[tid] - v;
}
__global__ void k_scan3(int n) {
    int i  = blockIdx.x * blockDim.x + threadIdx.x;
    int st = gridDim.x * blockDim.x;
    for (int k = i; k < n; k += st) {
        int r = g_excl[k] + g_bsum[k >> 10];
        g_rowstart[k] = r;
        g_cursor[k]   = r;
    }
    if (i == 0)
        g_rowstart[n] = g_excl[n - 1] + g_bsum[(n - 1) >> 10] + g_count[n - 1];
}
__global__ void k_scatter(const void* __restrict__ ei, int E, int n) {
    int is64 = g_is64;
    int i  = blockIdx.x * blockDim.x + threadIdx.x;
    int st = gridDim.x * blockDim.x;
    for (int e = i; e < E; e += st) {
        int d = load_idx(ei, e, is64);
        if ((unsigned)d >= (unsigned)n) continue;
        int s = load_idx(ei, (long long)E + e, is64);
        if ((unsigned)s >= (unsigned)n) s = d;
        int p = atomicAdd(&g_cursor[d], 1);
        if ((unsigned)p < (unsigned)EMAX) g_col[p] = s;
    }
}

// ---------------- weight prep ------------------------------------------------
__global__ void k_wprep(const float* __restrict__ W, int l) {
    int idx = blockIdx.x * blockDim.x + threadIdx.x;
    if (idx >= 16384) return;
    float v = W[idx];
    __nv_bfloat16 hi = __float2bfloat16_rn(v);
    __nv_bfloat16 lo = __float2bfloat16_rn(v - __bfloat162float(hi));
    g_Whi[l * 16384 + idx] = hi;
    g_Wlo[l * 16384 + idx] = lo;
}
__global__ void k_wprep40(const float* __restrict__ W) {   // [128][40] -> [128][48]
    int idx = blockIdx.x * blockDim.x + threadIdx.x;       // 6144
    if (idx >= 128 * 48) return;
    int k = idx / 48, c = idx % 48;
    float v = (c < 40) ? W[k * 40 + c] : 0.f;
    __nv_bfloat16 hi = __float2bfloat16_rn(v);
    __nv_bfloat16 lo = __float2bfloat16_rn(v - __bfloat162float(hi));
    g_W40hi[idx] = hi;
    g_W40lo[idx] = lo;
}

// ---------------- aggregation (+ fused BN+ReLU of prev layer), MLP=8 -------
__global__ void k_aggregate(const float* __restrict__ P, float* __restrict__ Q, int n,
                            const float* __restrict__ bnm, const float* __restrict__ bns) {
    int warp = (blockIdx.x * blockDim.x + threadIdx.x) >> 5;
    int lane = threadIdx.x & 31;
    if (warp >= n) return;
    bool dobn = (bnm != nullptr);
    float4 m4 = make_float4(0.f, 0.f, 0.f, 0.f);
    float4 s4 = make_float4(1.f, 1.f, 1.f, 1.f);
    if (dobn) {
        m4 = ((const float4*)bnm)[lane];
        s4 = ((const float4*)bns)[lane];
    }
    const float4* P4 = (const float4*)P;
    float4 acc = P4[(size_t)warp * 32 + lane];
    if (dobn) acc = bn_relu4(acc, m4, s4);
    int s = g_rowstart[warp];
    int t = g_rowstart[warp + 1];
    for (int p = s; p < t; p += 32) {
        int cnt = min(32, t - p);
        int j = (lane < cnt) ? g_col[p + lane] : 0;
        int q = 0;
        for (; q + 8 <= cnt; q += 8) {          // 8 independent loads in flight
            int jj[8];
#pragma unroll
            for (int u = 0; u < 8; u++) jj[u] = __shfl_sync(0xffffffffu, j, q + u);
            float4 r[8];
#pragma unroll
            for (int u = 0; u < 8; u++) r[u] = P4[(size_t)jj[u] * 32 + lane];
#pragma unroll
            for (int u = 0; u < 8; u++) {
                float4 v = dobn ? bn_relu4(r[u], m4, s4) : r[u];
                acc.x += v.x; acc.y += v.y; acc.z += v.z; acc.w += v.w;
            }
        }
        for (; q + 4 <= cnt; q += 4) {
            int j0 = __shfl_sync(0xffffffffu, j, q);
            int j1 = __shfl_sync(0xffffffffu, j, q + 1);
            int j2 = __shfl_sync(0xffffffffu, j, q + 2);
            int j3 = __shfl_sync(0xffffffffu, j, q + 3);
            float4 r0 = P4[(size_t)j0 * 32 + lane];
            float4 r1 = P4[(size_t)j1 * 32 + lane];
            float4 r2 = P4[(size_t)j2 * 32 + lane];
            float4 r3 = P4[(size_t)j3 * 32 + lane];
            if (dobn) {
                r0 = bn_relu4(r0, m4, s4); r1 = bn_relu4(r1, m4, s4);
                r2 = bn_relu4(r2, m4, s4); r3 = bn_relu4(r3, m4, s4);
            }
            acc.x += r0.x + r1.x + r2.x + r3.x;
            acc.y += r0.y + r1.y + r2.y + r3.y;
            acc.z += r0.z + r1.z + r2.z + r3.z;
            acc.w += r0.w + r1.w + r2.w + r3.w;
        }
        for (; q < cnt; q++) {
            int jj = __shfl_sync(0xffffffffu, j, q);
            float4 r = P4[(size_t)jj * 32 + lane];
            if (dobn) r = bn_relu4(r, m4, s4);
            acc.x += r.x; acc.y += r.y; acc.z += r.z; acc.w += r.w;
        }
    }
    ((float4*)Q)[(size_t)warp * 32 + lane] = acc;
}

// ---------------- persistent mma.sync bf16 GEMM + bias + BN stats -----------
// Last CTA to finish also computes bnm/bns (folds k_bnfin into the epilogue).
#define PA 136
#define ATILEB (64 * PA * 2)            // 17408 B
#define WTILEB (128 * PA * 2)           // 34816 B
#define OFF_AHI 0
#define OFF_ALO ATILEB
#define OFF_WHI (2 * ATILEB)
#define OFF_WLO (2 * ATILEB + WTILEB)
#define SMEM_MMA (2 * ATILEB + 2 * WTILEB)   // 104448 B -> 2 CTAs/SM

__global__ __launch_bounds__(128) void k_gemm_mma(
    float* __restrict__ A, const __nv_bfloat16* __restrict__ Whi,
    const __nv_bfloat16* __restrict__ Wlo, const float* __restrict__ bias,
    float* __restrict__ gsum, float* __restrict__ gsq, int n, int ntiles,
    float* __restrict__ bnm_out, float* __restrict__ bns_out,
    int* __restrict__ done)
{
    extern __shared__ char sm[];
    __shared__ int s_last;
    int tid  = threadIdx.x;
    int lane = tid & 31;
    int warp = tid >> 5;

    // ---- W hi/lo tiles: load once ------------------------------------------
    for (int i = tid; i < 4096; i += 128) {
        int k = i >> 5, c4 = (i & 31) * 4;
        uint2 h = *(const uint2*)((const char*)Whi + k * 256 + c4 * 2);
        uint2 l = *(const uint2*)((const char*)Wlo + k * 256 + c4 * 2);
        *(uint2*)(sm + OFF_WHI + k * (PA * 2) + c4 * 2) = h;
        *(uint2*)(sm + OFF_WLO + k * (PA * 2) + c4 * 2) = l;
    }

    int m  = lane >> 3, ri = lane & 7;
    int rowAl = warp * 16 + (m & 1) * 8 + ri;
    uint32_t aHiB = smem_u32(sm + OFF_AHI) + rowAl * (PA * 2) + (m >> 1) * 16;
    uint32_t aLoB = smem_u32(sm + OFF_ALO) + rowAl * (PA * 2) + (m >> 1) * 16;
    int rowB = lane & 15;
    uint32_t bHiB = smem_u32(sm + OFF_WHI) + rowB * (PA * 2) + (lane >> 4) * 16;
    uint32_t bLoB = smem_u32(sm + OFF_WLO) + rowB * (PA * 2) + (lane >> 4) * 16;

    const float4* A4 = (const float4*)A;
    float* sred  = (float*)sm;
    float* sredq = (float*)sm + 512;

    for (int tile = blockIdx.x; tile < ntiles; tile += gridDim.x) {
        int r0g = tile * 64;
        __syncthreads();   // previous iteration's stats reads done

        for (int i = tid; i < 2048; i += 128) {
            int row = i >> 5, c4 = (i & 31) * 4;
            float4 v = make_float4(0.f, 0.f, 0.f, 0.f);
            if (r0g + row < n) v = A4[(size_t)(r0g + row) * 32 + (i & 31)];
            __nv_bfloat16 h0 = __float2bfloat16_rn(v.x), h1 = __float2bfloat16_rn(v.y);
            __nv_bfloat16 h2 = __float2bfloat16_rn(v.z), h3 = __float2bfloat16_rn(v.w);
            __nv_bfloat16 l0 = __float2bfloat16_rn(v.x - __bfloat162float(h0));
            __nv_bfloat16 l1 = __float2bfloat16_rn(v.y - __bfloat162float(h1));
            __nv_bfloat16 l2 = __float2bfloat16_rn(v.z - __bfloat162float(h2));
            __nv_bfloat16 l3 = __float2bfloat16_rn(v.w - __bfloat162float(h3));
            uint2 ph = make_uint2(
                (uint32_t)__bfloat16_as_ushort(h0) | ((uint32_t)__bfloat16_as_ushort(h1) << 16),
                (uint32_t)__bfloat16_as_ushort(h2) | ((uint32_t)__bfloat16_as_ushort(h3) << 16));
            uint2 pl = make_uint2(
                (uint32_t)__bfloat16_as_ushort(l0) | ((uint32_t)__bfloat16_as_ushort(l1) << 16),
                (uint32_t)__bfloat16_as_ushort(l2) | ((uint32_t)__bfloat16_as_ushort(l3) << 16));
            *(uint2*)(sm + OFF_AHI + row * (PA * 2) + c4 * 2) = ph;
            *(uint2*)(sm + OFF_ALO + row * (PA * 2) + c4 * 2) = pl;
        }
        __syncthreads();

        float acc[16][4];
#pragma unroll
        for (int t = 0; t < 16; t++)
#pragma unroll
            for (int j = 0; j < 4; j++) acc[t][j] = 0.f;

#pragma unroll
        for (int kc = 0; kc < 8; kc++) {
            uint32_t ah[4], al[4];
            ldsm4(ah, aHiB + kc * 32);
            ldsm4(al, aLoB + kc * 32);
            uint32_t kb = kc * 16 * (PA * 2);
#pragma unroll
            for (int nt = 0; nt < 8; nt++) {
                uint32_t bh[4], bl[4];
                ldsm4t(bh, bHiB + kb + nt * 32);
                ldsm4t(bl, bLoB + kb + nt * 32);
                mma16816(acc[2 * nt],     ah, bh);
                mma16816(acc[2 * nt],     al, bh);
                mma16816(acc[2 * nt],     ah, bl);
                mma16816(acc[2 * nt + 1], ah, bh + 2);
                mma16816(acc[2 * nt + 1], al, bh + 2);
                mma16816(acc[2 * nt + 1], ah, bl + 2);
            }
        }
        __syncthreads();   // A tiles dead; sred aliases them

        int lr = lane >> 2;
        int lc = lane & 3;
        int row0 = r0g + warp * 16 + lr;
        int row1 = row0 + 8;
        bool v0 = row0 < n, v1 = row1 < n;
#pragma unroll
        for (int nt = 0; nt < 16; nt++) {
            int c0 = nt * 8 + lc * 2;
            float b0v = __ldg(bias + c0), b1v = __ldg(bias + c0 + 1);
            float y00 = acc[nt][0] + b0v, y01 = acc[nt][1] + b1v;
            float y10 = acc[nt][2] + b0v, y11 = acc[nt][3] + b1v;
            if (v0) *(float2*)&A[(size_t)row0 * 128 + c0] = make_float2(y00, y01);
            if (v1) *(float2*)&A[(size_t)row1 * 128 + c0] = make_float2(y10, y11);
            float s0 = (v0 ? y00 : 0.f) + (v1 ? y10 : 0.f);
            float s1 = (v0 ? y01 : 0.f) + (v1 ? y11 : 0.f);
            float q0 = (v0 ? y00 * y00 : 0.f) + (v1 ? y10 * y10 : 0.f);
            float q1 = (v0 ? y01 * y01 : 0.f) + (v1 ? y11 * y11 : 0.f);
#pragma unroll
            for (int o = 4; o < 32; o <<= 1) {
                s0 += __shfl_xor_sync(0xffffffffu, s0, o);
                s1 += __shfl_xor_sync(0xffffffffu, s1, o);
                q0 += __shfl_xor_sync(0xffffffffu, q0, o);
                q1 += __shfl_xor_sync(0xffffffffu, q1, o);
            }
            if (lr == 0) {
                sred [warp * 128 + c0]     = s0;
                sred [warp * 128 + c0 + 1] = s1;
                sredq[warp * 128 + c0]     = q0;
                sredq[warp * 128 + c0 + 1] = q1;
            }
        }
        __syncthreads();
        if (tid < 128) {
            float s = 0.f, q = 0.f;
#pragma unroll
            for (int w = 0; w < 4; w++) {
                s += sred [w * 128 + tid];
                q += sredq[w * 128 + tid];
            }
            atomicAdd(&gsum[tid], s);
            atomicAdd(&gsq[tid], q);
        }
    }

    // ---- fold BN finalize into the last CTA ---------------------------------
    __syncthreads();
    if (tid == 0) {
        __threadfence();
        int v = atomicAdd(done, 1);
        s_last = (v == gridDim.x - 1) ? 1 : 0;
    }
    __syncthreads();
    if (s_last) {
        __threadfence();
        if (tid < 128) {
            float inv_n = 1.0f / (float)n;
            float mval = gsum[tid] * inv_n;
            float vvar = gsq[tid] * inv_n - mval * mval;
            bnm_out[tid] = mval;
            bns_out[tid] = rsqrtf(vvar + 1e-5f);
        }
    }
}

// ---------------- persistent final GEMM 128->40 via mma (BN+ReLU fused) -----
// Same smem layout/addressing as k_gemm_mma; W tiles (48 padded cols) + BN
// params loaded once per CTA; 3 ldsm-groups (48 cols), writes 40 valid cols.
__global__ __launch_bounds__(128) void k_gemm40p(
    const float* __restrict__ A, const float* __restrict__ bias,
    float* __restrict__ out, int n, int ntiles,
    const float* __restrict__ bnm, const float* __restrict__ bns)
{
    extern __shared__ char sm[];
    __shared__ float s_bnm[128], s_bns[128];
    int tid  = threadIdx.x;
    int lane = tid & 31;
    int warp = tid >> 5;

    if (tid < 128) {
        s_bnm[tid] = bnm[tid];
        s_bns[tid] = bns[tid];
    }
    // W40 hi/lo tiles: 128 rows x 48 cols, pitch PA. 1536 uint2 each.
    for (int i = tid; i < 1536; i += 128) {
        int k = i / 12, c4 = (i % 12) * 4;
        uint2 h = *(const uint2*)((const char*)g_W40hi + k * 96 + c4 * 2);
        uint2 l = *(const uint2*)((const char*)g_W40lo + k * 96 + c4 * 2);
        *(uint2*)(sm + OFF_WHI + k * (PA * 2) + c4 * 2) = h;
        *(uint2*)(sm + OFF_WLO + k * (PA * 2) + c4 * 2) = l;
    }

    int m  = lane >> 3, ri = lane & 7;
    int rowAl = warp * 16 + (m & 1) * 8 + ri;
    uint32_t aHiB = smem_u32(sm + OFF_AHI) + rowAl * (PA * 2) + (m >> 1) * 16;
    uint32_t aLoB = smem_u32(sm + OFF_ALO) + rowAl * (PA * 2) + (m >> 1) * 16;
    int rowB = lane & 15;
    uint32_t bHiB = smem_u32(sm + OFF_WHI) + rowB * (PA * 2) + (lane >> 4) * 16;
    uint32_t bLoB = smem_u32(sm + OFF_WLO) + rowB * (PA * 2) + (lane >> 4) * 16;

    const float4* A4 = (const float4*)A;

    for (int tile = blockIdx.x; tile < ntiles; tile += gridDim.x) {
        int r0g = tile * 64;
        __syncthreads();   // A tiles free (also covers first-iter W/bn writes)

        // fill A hi/lo with BN+ReLU applied (smem-cached params)
        for (int i = tid; i < 2048; i += 128) {
            int row = i >> 5, c4i = i & 31;
            float4 v = make_float4(0.f, 0.f, 0.f, 0.f);
            if (r0g + row < n) {
                v = A4[(size_t)(r0g + row) * 32 + c4i];
                float4 mm = ((const float4*)s_bnm)[c4i];
                float4 ss = ((const float4*)s_bns)[c4i];
                v = bn_relu4(v, mm, ss);
            }
            __nv_bfloat16 h0 = __float2bfloat16_rn(v.x), h1 = __float2bfloat16_rn(v.y);
            __nv_bfloat16 h2 = __float2bfloat16_rn(v.z), h3 = __float2bfloat16_rn(v.w);
            __nv_bfloat16 l0 = __float2bfloat16_rn(v.x - __bfloat162float(h0));
            __nv_bfloat16 l1 = __float2bfloat16_rn(v.y - __bfloat162float(h1));
            __nv_bfloat16 l2 = __float2bfloat16_rn(v.z - __bfloat162float(h2));
            __nv_bfloat16 l3 = __float2bfloat16_rn(v.w - __bfloat162float(h3));
            uint2 ph = make_uint2(
                (uint32_t)__bfloat16_as_ushort(h0) | ((uint32_t)__bfloat16_as_ushort(h1) << 16),
                (uint32_t)__bfloat16_as_ushort(h2) | ((uint32_t)__bfloat16_as_ushort(h3) << 16));
            uint2 pl = make_uint2(
                (uint32_t)__bfloat16_as_ushort(l0) | ((uint32_t)__bfloat16_as_ushort(l1) << 16),
                (uint32_t)__bfloat16_as_ushort(l2) | ((uint32_t)__bfloat16_as_ushort(l3) << 16));
            *(uint2*)(sm + OFF_AHI + row * (PA * 2) + c4i * 8) = ph;
            *(uint2*)(sm + OFF_ALO + row * (PA * 2) + c4i * 8) = pl;
        }
        __syncthreads();

        float acc[6][4];
#pragma unroll
        for (int t = 0; t < 6; t++)
#pragma unroll
            for (int j = 0; j < 4; j++) acc[t][j] = 0.f;

#pragma unroll
        for (int kc = 0; kc < 8; kc++) {
            uint32_t ah[4], al[4];
            ldsm4(ah, aHiB + kc * 32);
            ldsm4(al, aLoB + kc * 32);
            uint32_t kb = kc * 16 * (PA * 2);
#pragma unroll
            for (int nt = 0; nt < 3; nt++) {
                uint32_t bh[4], bl[4];
                ldsm4t(bh, bHiB + kb + nt * 32);
                ldsm4t(bl, bLoB + kb + nt * 32);
                mma16816(acc[2 * nt],     ah, bh);
                mma16816(acc[2 * nt],     al, bh);
                mma16816(acc[2 * nt],     ah, bl);
                mma16816(acc[2 * nt + 1], ah, bh + 2);
                mma16816(acc[2 * nt + 1], al, bh + 2);
                mma16816(acc[2 * nt + 1], ah, bl + 2);
            }
        }

        int lr = lane >> 2;
        int lc = lane & 3;
        int row0 = r0g + warp * 16 + lr;
        int row1 = row0 + 8;
        bool v0 = row0 < n, v1 = row1 < n;
#pragma unroll
        for (int nt = 0; nt < 5; nt++) {       // cols 0..39 only
            int c0 = nt * 8 + lc * 2;
            if (c0 >= 40) continue;
            float b0v = __ldg(bias + c0), b1v = __ldg(bias + c0 + 1);
            float y00 = acc[nt][0] + b0v, y01 = acc[nt][1] + b1v;
            float y10 = acc[nt][2] + b0v, y11 = acc[nt][3] + b1v;
            if (v0) *(float2*)&out[(size_t)row0 * 40 + c0] = make_float2(y00, y01);
            if (v1) *(float2*)&out[(size_t)row1 * 40 + c0] = make_float2(y10, y11);
        }
    }
}

// ---------------- launcher -------------------------------------------------
extern "C" void kernel_launch(void* const* d_in, const int* in_sizes, int n_in,
                              void* d_out, int out_size)
{
    const float* x  = (const float*)d_in[0];
    const void*  ei = d_in[1];
    const float* W0 = (const float*)d_in[2];
    const float* b0 = (const float*)d_in[3];
    const float* W1 = (const float*)d_in[4];
    const float* b1 = (const float*)d_in[5];
    const float* W2 = (const float*)d_in[6];
    const float* b2 = (const float*)d_in[7];
    const float* Wl = (const float*)d_in[8];
    const float* bl = (const float*)d_in[9];
    float* out = (float*)d_out;

    int n = in_sizes[0] / HDIM;
    int E = in_sizes[1] / 2;

    float *bufA, *bufB, *sums, *bnm, *bns;
    __nv_bfloat16 *whi, *wlo;
    int* done;
    cudaGetSymbolAddress((void**)&bufA, g_bufA);
    cudaGetSymbolAddress((void**)&bufB, g_bufB);
    cudaGetSymbolAddress((void**)&sums, g_sums);
    cudaGetSymbolAddress((void**)&bnm,  g_bnm);
    cudaGetSymbolAddress((void**)&bns,  g_bns);
    cudaGetSymbolAddress((void**)&whi,  g_Whi);
    cudaGetSymbolAddress((void**)&wlo,  g_Wlo);
    cudaGetSymbolAddress((void**)&done, g_done);

    cudaFuncSetAttribute(k_gemm_mma, cudaFuncAttributeMaxDynamicSharedMemorySize, SMEM_MMA);
    cudaFuncSetAttribute(k_gemm40p,  cudaFuncAttributeMaxDynamicSharedMemorySize, SMEM_MMA);

    // side stream for weight-prep overlap with CSR build (host objects only)
    static cudaStream_t s2 = nullptr;
    static cudaEvent_t  evF = nullptr, evW = nullptr;
    if (s2 == nullptr) {
        cudaStreamCreateWithFlags(&s2, cudaStreamNonBlocking);
        cudaEventCreateWithFlags(&evF, cudaEventDisableTiming);
        cudaEventCreateWithFlags(&evW, cudaEventDisableTiming);
    }

    int nb = (n + 1023) >> 10;

    k_init<<<256, 256>>>(n);
    // fork: weight prep on s2 overlaps the CSR build on the main stream
    cudaEventRecord(evF, 0);
    cudaStreamWaitEvent(s2, evF, 0);
    k_wprep<<<64, 256, 0, s2>>>(W0, 0);
    k_wprep<<<64, 256, 0, s2>>>(W1, 1);
    k_wprep<<<64, 256, 0, s2>>>(W2, 2);
    k_wprep40<<<24, 256, 0, s2>>>(Wl);
    cudaEventRecord(evW, s2);

    k_detect<<<16, 256>>>((const unsigned*)ei, in_sizes[1]);
    k_count<<<(E + 255) / 256, 256>>>(ei, E, n);
    k_scan1<<<nb, 256>>>(n);
    k_scan2<<<1, 128>>>(nb);
    k_scan3<<<(n + 255) / 256, 256>>>(n);
    k_scatter<<<(E + 255) / 256, 256>>>(ei, E, n);
    cudaStreamWaitEvent(0, evW, 0);        // join: GEMMs need prepped weights

    const float* bs_[3] = { b0, b1, b2 };
    float* bufs[2] = { bufA, bufB };
    const float* P = x;
    int ntiles = (n + 63) / 64;
    int ggrid  = ntiles < 296 ? ntiles : 296;   // 2 CTAs/SM persistent
    for (int l = 0; l < 3; l++) {
        float* Q = bufs[l & 1];
        const float* pm  = (l == 0) ? nullptr : bnm + (l - 1) * 128;
        const float* psd = (l == 0) ? nullptr : bns + (l - 1) * 128;
        k_aggregate<<<(n * 32 + 255) / 256, 256>>>(P, Q, n, pm, psd);
        k_gemm_mma<<<ggrid, 128, SMEM_MMA>>>(Q, whi + l * 16384, wlo + l * 16384,
                                             bs_[l], sums + l * 256,
                                             sums + l * 256 + 128, n, ntiles,
                                             bnm + l * 128, bns + l * 128,
                                             done + l);
        P = Q;
    }
    k_gemm40p<<<ggrid, 128, SMEM_MMA>>>(P, bl, out, n, ntiles,
                                        bnm + 2 * 128, bns + 2 * 128);
}

// round 14
// speedup vs baseline: 1.3996x; 1.0046x over previous
#include <cuda_runtime.h>
#include <cuda_bf16.h>
#include <cstdint>

#define NMAX 100000
#define EMAX 800000
#define HDIM 128

// ---------------- static device scratch ------------------------------------
__device__ float g_bufA[NMAX * HDIM];
__device__ float g_bufB[NMAX * HDIM];
__device__ int   g_count[NMAX];
__device__ int   g_excl[NMAX];
__device__ int   g_rowstart[NMAX + 1];
__device__ int   g_cursor[NMAX];
__device__ int   g_col[EMAX];
__device__ int   g_bsum[128];
__device__ float g_sums[6 * 128];            // [layer][sum(128)|sumsq(128)]
__device__ float g_bnm[3 * 128];             // per-layer mean
__device__ float g_bns[3 * 128];             // per-layer rsqrt(var+eps)
__device__ __nv_bfloat16 g_Whi[3 * 16384];   // row-major [k][n] bf16 hi
__device__ __nv_bfloat16 g_Wlo[3 * 16384];   // row-major [k][n] bf16 lo
__device__ __nv_bfloat16 g_W40hi[128 * 48];  // final layer, padded to 48 cols
__device__ __nv_bfloat16 g_W40lo[128 * 48];
__device__ int   g_done[3];                  // per-layer GEMM completion ctr
__device__ int   g_scanctr;                  // scan12 last-block counter

// ---------------- helpers ---------------------------------------------------
__device__ __forceinline__ uint32_t smem_u32(const void* p) {
    uint32_t a;
    asm("{ .reg .u64 t; cvta.to.shared.u64 t, %1; cvt.u32.u64 %0, t; }" : "=r"(a) : "l"(p));
    return a;
}
__device__ __forceinline__ void ldsm4(uint32_t* r, uint32_t addr) {
    asm volatile("ldmatrix.sync.aligned.m8n8.x4.shared.b16 {%0,%1,%2,%3}, [%4];"
                 : "=r"(r[0]), "=r"(r[1]), "=r"(r[2]), "=r"(r[3]) : "r"(addr));
}
__device__ __forceinline__ void ldsm4t(uint32_t* r, uint32_t addr) {
    asm volatile("ldmatrix.sync.aligned.m8n8.x4.trans.shared.b16 {%0,%1,%2,%3}, [%4];"
                 : "=r"(r[0]), "=r"(r[1]), "=r"(r[2]), "=r"(r[3]) : "r"(addr));
}
__device__ __forceinline__ void mma16816(float* d, const uint32_t* a, const uint32_t* b) {
    asm volatile("mma.sync.aligned.m16n8k16.row.col.f32.bf16.bf16.f32 "
                 "{%0,%1,%2,%3}, {%4,%5,%6,%7}, {%8,%9}, {%0,%1,%2,%3};"
                 : "+f"(d[0]), "+f"(d[1]), "+f"(d[2]), "+f"(d[3])
                 : "r"(a[0]), "r"(a[1]), "r"(a[2]), "r"(a[3]), "r"(b[0]), "r"(b[1]));
}
__device__ __forceinline__ float4 bn_relu4(float4 v, float4 m4, float4 s4) {
    v.x = fmaxf((v.x - m4.x) * s4.x, 0.f);
    v.y = fmaxf((v.y - m4.y) * s4.y, 0.f);
    v.z = fmaxf((v.z - m4.z) * s4.z, 0.f);
    v.w = fmaxf((v.w - m4.w) * s4.w, 0.f);
    return v;
}

// int64 edge buffers (values < 2^32) have zero high words at odd 32-bit
// positions; for int32 data those words are random edge indices.
// Checking 3 fixed positions is deterministic and safe (p(false int64) ~ 1e-15).
__device__ __forceinline__ int detect64(const unsigned* __restrict__ w) {
    return (w[1] | w[3] | w[5]) == 0u;
}
__device__ __forceinline__ int load_idx(const void* ei, long long pos, int is64) {
    if (is64) return ((const int*)ei)[2 * pos];   // little-endian low word
    return ((const int*)ei)[pos];
}

// ---------------- init ------------------------------------------------------
__global__ void k_init(int n) {
    int i  = blockIdx.x * blockDim.x + threadIdx.x;
    int st = gridDim.x * blockDim.x;
    for (int k = i; k < n; k += st) g_count[k] = 0;
    for (int k = i; k < 6 * 128; k += st) g_sums[k] = 0.f;
    if (i == 0) {
        g_done[0] = g_done[1] = g_done[2] = 0;
        g_scanctr = 0;
    }
}

// ---------------- CSR build ------------------------------------------------
__global__ void k_count(const void* __restrict__ ei, int E, int n) {
    int is64 = detect64((const unsigned*)ei);
    int i  = blockIdx.x * blockDim.x + threadIdx.x;
    int st = gridDim.x * blockDim.x;
    for (int e = i; e < E; e += st) {
        int d = load_idx(ei, e, is64);
        if ((unsigned)d < (unsigned)n) atomicAdd(&g_count[d], 1);
    }
}

// scan1 + scan2 fused: per-block 1024-wide exclusive scan; the LAST block to
// finish also scans the 98 block totals.
__global__ void k_scan12(int n) {
    __shared__ int s[256];
    __shared__ int s_last;
    int tid  = threadIdx.x;
    int base = blockIdx.x * 1024 + tid * 4;
    int v[4];
#pragma unroll
    for (int i = 0; i < 4; i++) v[i] = (base + i < n) ? g_count[base + i] : 0;
    int tsum = v[0] + v[1] + v[2] + v[3];
    s[tid] = tsum;
    __syncthreads();
#pragma unroll
    for (int off = 1; off < 256; off <<= 1) {
        int x = (tid >= off) ? s[tid - off] : 0;
        __syncthreads();
        s[tid] += x;
        __syncthreads();
    }
    int run = s[tid] - tsum;
#pragma unroll
    for (int i = 0; i < 4; i++) {
        if (base + i < n) g_excl[base + i] = run;
        run += v[i];
    }
    if (tid == 255) {
        g_bsum[blockIdx.x] = s[255];
        __threadfence();               // publish bsum before the counter bump
    }
    __syncthreads();
    if (tid == 0) {
        int c = atomicAdd(&g_scanctr, 1);
        s_last = (c == gridDim.x - 1) ? 1 : 0;
    }
    __syncthreads();
    if (s_last) {
        __threadfence();               // acquire: see all blocks' bsum
        int nb = gridDim.x;
        int vv = (tid < nb) ? g_bsum[tid] : 0;
        __syncthreads();               // s[] reuse
        s[tid] = vv;
        __syncthreads();
#pragma unroll
        for (int off = 1; off < 256; off <<= 1) {
            int x = (tid >= off) ? s[tid - off] : 0;
            __syncthreads();
            s[tid] += x;
            __syncthreads();
        }
        if (tid < nb) g_bsum[tid] = s[tid] - vv;
    }
}
__global__ void k_scan3(int n) {
    int i  = blockIdx.x * blockDim.x + threadIdx.x;
    int st = gridDim.x * blockDim.x;
    for (int k = i; k < n; k += st) {
        int r = g_excl[k] + g_bsum[k >> 10];
        g_rowstart[k] = r;
        g_cursor[k]   = r;
    }
    if (i == 0)
        g_rowstart[n] = g_excl[n - 1] + g_bsum[(n - 1) >> 10] + g_count[n - 1];
}
__global__ void k_scatter(const void* __restrict__ ei, int E, int n) {
    int is64 = detect64((const unsigned*)ei);
    int i  = blockIdx.x * blockDim.x + threadIdx.x;
    int st = gridDim.x * blockDim.x;
    for (int e = i; e < E; e += st) {
        int d = load_idx(ei, e, is64);
        if ((unsigned)d >= (unsigned)n) continue;
        int s = load_idx(ei, (long long)E + e, is64);
        if ((unsigned)s >= (unsigned)n) s = d;
        int p = atomicAdd(&g_cursor[d], 1);
        if ((unsigned)p < (unsigned)EMAX) g_col[p] = s;
    }
}

// ---------------- weight prep ------------------------------------------------
__global__ void k_wprep(const float* __restrict__ W, int l) {
    int idx = blockIdx.x * blockDim.x + threadIdx.x;
    if (idx >= 16384) return;
    float v = W[idx];
    __nv_bfloat16 hi = __float2bfloat16_rn(v);
    __nv_bfloat16 lo = __float2bfloat16_rn(v - __bfloat162float(hi));
    g_Whi[l * 16384 + idx] = hi;
    g_Wlo[l * 16384 + idx] = lo;
}
__global__ void k_wprep40(const float* __restrict__ W) {   // [128][40] -> [128][48]
    int idx = blockIdx.x * blockDim.x + threadIdx.x;       // 6144
    if (idx >= 128 * 48) return;
    int k = idx / 48, c = idx % 48;
    float v = (c < 40) ? W[k * 40 + c] : 0.f;
    __nv_bfloat16 hi = __float2bfloat16_rn(v);
    __nv_bfloat16 lo = __float2bfloat16_rn(v - __bfloat162float(hi));
    g_W40hi[idx] = hi;
    g_W40lo[idx] = lo;
}

// ---------------- aggregation (+ fused BN+ReLU of prev layer), MLP=8 -------
__global__ void k_aggregate(const float* __restrict__ P, float* __restrict__ Q, int n,
                            const float* __restrict__ bnm, const float* __restrict__ bns) {
    int warp = (blockIdx.x * blockDim.x + threadIdx.x) >> 5;
    int lane = threadIdx.x & 31;
    if (warp >= n) return;
    bool dobn = (bnm != nullptr);
    float4 m4 = make_float4(0.f, 0.f, 0.f, 0.f);
    float4 s4 = make_float4(1.f, 1.f, 1.f, 1.f);
    if (dobn) {
        m4 = ((const float4*)bnm)[lane];
        s4 = ((const float4*)bns)[lane];
    }
    const float4* P4 = (const float4*)P;
    float4 acc = P4[(size_t)warp * 32 + lane];
    if (dobn) acc = bn_relu4(acc, m4, s4);
    int s = g_rowstart[warp];
    int t = g_rowstart[warp + 1];
    for (int p = s; p < t; p += 32) {
        int cnt = min(32, t - p);
        int j = (lane < cnt) ? g_col[p + lane] : 0;
        int q = 0;
        for (; q + 8 <= cnt; q += 8) {          // 8 independent loads in flight
            int jj[8];
#pragma unroll
            for (int u = 0; u < 8; u++) jj[u] = __shfl_sync(0xffffffffu, j, q + u);
            float4 r[8];
#pragma unroll
            for (int u = 0; u < 8; u++) r[u] = P4[(size_t)jj[u] * 32 + lane];
#pragma unroll
            for (int u = 0; u < 8; u++) {
                float4 v = dobn ? bn_relu4(r[u], m4, s4) : r[u];
                acc.x += v.x; acc.y += v.y; acc.z += v.z; acc.w += v.w;
            }
        }
        for (; q + 4 <= cnt; q += 4) {
            int j0 = __shfl_sync(0xffffffffu, j, q);
            int j1 = __shfl_sync(0xffffffffu, j, q + 1);
            int j2 = __shfl_sync(0xffffffffu, j, q + 2);
            int j3 = __shfl_sync(0xffffffffu, j, q + 3);
            float4 r0 = P4[(size_t)j0 * 32 + lane];
            float4 r1 = P4[(size_t)j1 * 32 + lane];
            float4 r2 = P4[(size_t)j2 * 32 + lane];
            float4 r3 = P4[(size_t)j3 * 32 + lane];
            if (dobn) {
                r0 = bn_relu4(r0, m4, s4); r1 = bn_relu4(r1, m4, s4);
                r2 = bn_relu4(r2, m4, s4); r3 = bn_relu4(r3, m4, s4);
            }
            acc.x += r0.x + r1.x + r2.x + r3.x;
            acc.y += r0.y + r1.y + r2.y + r3.y;
            acc.z += r0.z + r1.z + r2.z + r3.z;
            acc.w += r0.w + r1.w + r2.w + r3.w;
        }
        for (; q < cnt; q++) {
            int jj = __shfl_sync(0xffffffffu, j, q);
            float4 r = P4[(size_t)jj * 32 + lane];
            if (dobn) r = bn_relu4(r, m4, s4);
            acc.x += r.x; acc.y += r.y; acc.z += r.z; acc.w += r.w;
        }
    }
    ((float4*)Q)[(size_t)warp * 32 + lane] = acc;
}

// ---------------- persistent mma.sync bf16 GEMM + bias + BN stats -----------
#define PA 136
#define ATILEB (64 * PA * 2)            // 17408 B
#define WTILEB (128 * PA * 2)           // 34816 B
#define OFF_AHI 0
#define OFF_ALO ATILEB
#define OFF_WHI (2 * ATILEB)
#define OFF_WLO (2 * ATILEB + WTILEB)
#define SMEM_MMA (2 * ATILEB + 2 * WTILEB)   // 104448 B -> 2 CTAs/SM

__global__ __launch_bounds__(128) void k_gemm_mma(
    float* __restrict__ A, const __nv_bfloat16* __restrict__ Whi,
    const __nv_bfloat16* __restrict__ Wlo, const float* __restrict__ bias,
    float* __restrict__ gsum, float* __restrict__ gsq, int n, int ntiles,
    float* __restrict__ bnm_out, float* __restrict__ bns_out,
    int* __restrict__ done)
{
    extern __shared__ char sm[];
    __shared__ int s_last;
    int tid  = threadIdx.x;
    int lane = tid & 31;
    int warp = tid >> 5;

    for (int i = tid; i < 4096; i += 128) {
        int k = i >> 5, c4 = (i & 31) * 4;
        uint2 h = *(const uint2*)((const char*)Whi + k * 256 + c4 * 2);
        uint2 l = *(const uint2*)((const char*)Wlo + k * 256 + c4 * 2);
        *(uint2*)(sm + OFF_WHI + k * (PA * 2) + c4 * 2) = h;
        *(uint2*)(sm + OFF_WLO + k * (PA * 2) + c4 * 2) = l;
    }

    int m  = lane >> 3, ri = lane & 7;
    int rowAl = warp * 16 + (m & 1) * 8 + ri;
    uint32_t aHiB = smem_u32(sm + OFF_AHI) + rowAl * (PA * 2) + (m >> 1) * 16;
    uint32_t aLoB = smem_u32(sm + OFF_ALO) + rowAl * (PA * 2) + (m >> 1) * 16;
    int rowB = lane & 15;
    uint32_t bHiB = smem_u32(sm + OFF_WHI) + rowB * (PA * 2) + (lane >> 4) * 16;
    uint32_t bLoB = smem_u32(sm + OFF_WLO) + rowB * (PA * 2) + (lane >> 4) * 16;

    const float4* A4 = (const float4*)A;
    float* sred  = (float*)sm;
    float* sredq = (float*)sm + 512;

    for (int tile = blockIdx.x; tile < ntiles; tile += gridDim.x) {
        int r0g = tile * 64;
        __syncthreads();

        for (int i = tid; i < 2048; i += 128) {
            int row = i >> 5, c4 = (i & 31) * 4;
            float4 v = make_float4(0.f, 0.f, 0.f, 0.f);
            if (r0g + row < n) v = A4[(size_t)(r0g + row) * 32 + (i & 31)];
            __nv_bfloat16 h0 = __float2bfloat16_rn(v.x), h1 = __float2bfloat16_rn(v.y);
            __nv_bfloat16 h2 = __float2bfloat16_rn(v.z), h3 = __float2bfloat16_rn(v.w);
            __nv_bfloat16 l0 = __float2bfloat16_rn(v.x - __bfloat162float(h0));
            __nv_bfloat16 l1 = __float2bfloat16_rn(v.y - __bfloat162float(h1));
            __nv_bfloat16 l2 = __float2bfloat16_rn(v.z - __bfloat162float(h2));
            __nv_bfloat16 l3 = __float2bfloat16_rn(v.w - __bfloat162float(h3));
            uint2 ph = make_uint2(
                (uint32_t)__bfloat16_as_ushort(h0) | ((uint32_t)__bfloat16_as_ushort(h1) << 16),
                (uint32_t)__bfloat16_as_ushort(h2) | ((uint32_t)__bfloat16_as_ushort(h3) << 16));
            uint2 pl = make_uint2(
                (uint32_t)__bfloat16_as_ushort(l0) | ((uint32_t)__bfloat16_as_ushort(l1) << 16),
                (uint32_t)__bfloat16_as_ushort(l2) | ((uint32_t)__bfloat16_as_ushort(l3) << 16));
            *(uint2*)(sm + OFF_AHI + row * (PA * 2) + c4 * 2) = ph;
            *(uint2*)(sm + OFF_ALO + row * (PA * 2) + c4 * 2) = pl;
        }
        __syncthreads();

        float acc[16][4];
#pragma unroll
        for (int t = 0; t < 16; t++)
#pragma unroll
            for (int j = 0; j < 4; j++) acc[t][j] = 0.f;

#pragma unroll
        for (int kc = 0; kc < 8; kc++) {
            uint32_t ah[4], al[4];
            ldsm4(ah, aHiB + kc * 32);
            ldsm4(al, aLoB + kc * 32);
            uint32_t kb = kc * 16 * (PA * 2);
#pragma unroll
            for (int nt = 0; nt < 8; nt++) {
                uint32_t bh[4], bl[4];
                ldsm4t(bh, bHiB + kb + nt * 32);
                ldsm4t(bl, bLoB + kb + nt * 32);
                mma16816(acc[2 * nt],     ah, bh);
                mma16816(acc[2 * nt],     al, bh);
                mma16816(acc[2 * nt],     ah, bl);
                mma16816(acc[2 * nt + 1], ah, bh + 2);
                mma16816(acc[2 * nt + 1], al, bh + 2);
                mma16816(acc[2 * nt + 1], ah, bl + 2);
            }
        }
        __syncthreads();

        int lr = lane >> 2;
        int lc = lane & 3;
        int row0 = r0g + warp * 16 + lr;
        int row1 = row0 + 8;
        bool v0 = row0 < n, v1 = row1 < n;
#pragma unroll
        for (int nt = 0; nt < 16; nt++) {
            int c0 = nt * 8 + lc * 2;
            float b0v = __ldg(bias + c0), b1v = __ldg(bias + c0 + 1);
            float y00 = acc[nt][0] + b0v, y01 = acc[nt][1] + b1v;
            float y10 = acc[nt][2] + b0v, y11 = acc[nt][3] + b1v;
            if (v0) *(float2*)&A[(size_t)row0 * 128 + c0] = make_float2(y00, y01);
            if (v1) *(float2*)&A[(size_t)row1 * 128 + c0] = make_float2(y10, y11);
            float s0 = (v0 ? y00 : 0.f) + (v1 ? y10 : 0.f);
            float s1 = (v0 ? y01 : 0.f) + (v1 ? y11 : 0.f);
            float q0 = (v0 ? y00 * y00 : 0.f) + (v1 ? y10 * y10 : 0.f);
            float q1 = (v0 ? y01 * y01 : 0.f) + (v1 ? y11 * y11 : 0.f);
#pragma unroll
            for (int o = 4; o < 32; o <<= 1) {
                s0 += __shfl_xor_sync(0xffffffffu, s0, o);
                s1 += __shfl_xor_sync(0xffffffffu, s1, o);
                q0 += __shfl_xor_sync(0xffffffffu, q0, o);
                q1 += __shfl_xor_sync(0xffffffffu, q1, o);
            }
            if (lr == 0) {
                sred [warp * 128 + c0]     = s0;
                sred [warp * 128 + c0 + 1] = s1;
                sredq[warp * 128 + c0]     = q0;
                sredq[warp * 128 + c0 + 1] = q1;
            }
        }
        __syncthreads();
        if (tid < 128) {
            float s = 0.f, q = 0.f;
#pragma unroll
            for (int w = 0; w < 4; w++) {
                s += sred [w * 128 + tid];
                q += sredq[w * 128 + tid];
            }
            atomicAdd(&gsum[tid], s);
            atomicAdd(&gsq[tid], q);
        }
    }

    // ---- fold BN finalize into the last CTA ---------------------------------
    __syncthreads();
    if (tid == 0) {
        __threadfence();
        int v = atomicAdd(done, 1);
        s_last = (v == gridDim.x - 1) ? 1 : 0;
    }
    __syncthreads();
    if (s_last) {
        __threadfence();
        if (tid < 128) {
            float inv_n = 1.0f / (float)n;
            float mval = gsum[tid] * inv_n;
            float vvar = gsq[tid] * inv_n - mval * mval;
            bnm_out[tid] = mval;
            bns_out[tid] = rsqrtf(vvar + 1e-5f);
        }
    }
}

// ---------------- persistent final GEMM 128->40 via mma (BN+ReLU fused) -----
__global__ __launch_bounds__(128) void k_gemm40p(
    const float* __restrict__ A, const float* __restrict__ bias,
    float* __restrict__ out, int n, int ntiles,
    const float* __restrict__ bnm, const float* __restrict__ bns)
{
    extern __shared__ char sm[];
    __shared__ float s_bnm[128], s_bns[128];
    int tid  = threadIdx.x;
    int lane = tid & 31;
    int warp = tid >> 5;

    if (tid < 128) {
        s_bnm[tid] = bnm[tid];
        s_bns[tid] = bns[tid];
    }
    for (int i = tid; i < 1536; i += 128) {
        int k = i / 12, c4 = (i % 12) * 4;
        uint2 h = *(const uint2*)((const char*)g_W40hi + k * 96 + c4 * 2);
        uint2 l = *(const uint2*)((const char*)g_W40lo + k * 96 + c4 * 2);
        *(uint2*)(sm + OFF_WHI + k * (PA * 2) + c4 * 2) = h;
        *(uint2*)(sm + OFF_WLO + k * (PA * 2) + c4 * 2) = l;
    }

    int m  = lane >> 3, ri = lane & 7;
    int rowAl = warp * 16 + (m & 1) * 8 + ri;
    uint32_t aHiB = smem_u32(sm + OFF_AHI) + rowAl * (PA * 2) + (m >> 1) * 16;
    uint32_t aLoB = smem_u32(sm + OFF_ALO) + rowAl * (PA * 2) + (m >> 1) * 16;
    int rowB = lane & 15;
    uint32_t bHiB = smem_u32(sm + OFF_WHI) + rowB * (PA * 2) + (lane >> 4) * 16;
    uint32_t bLoB = smem_u32(sm + OFF_WLO) + rowB * (PA * 2) + (lane >> 4) * 16;

    const float4* A4 = (const float4*)A;

    for (int tile = blockIdx.x; tile < ntiles; tile += gridDim.x) {
        int r0g = tile * 64;
        __syncthreads();

        for (int i = tid; i < 2048; i += 128) {
            int row = i >> 5, c4i = i & 31;
            float4 v = make_float4(0.f, 0.f, 0.f, 0.f);
            if (r0g + row < n) {
                v = A4[(size_t)(r0g + row) * 32 + c4i];
                float4 mm = ((const float4*)s_bnm)[c4i];
                float4 ss = ((const float4*)s_bns)[c4i];
                v = bn_relu4(v, mm, ss);
            }
            __nv_bfloat16 h0 = __float2bfloat16_rn(v.x), h1 = __float2bfloat16_rn(v.y);
            __nv_bfloat16 h2 = __float2bfloat16_rn(v.z), h3 = __float2bfloat16_rn(v.w);
            __nv_bfloat16 l0 = __float2bfloat16_rn(v.x - __bfloat162float(h0));
            __nv_bfloat16 l1 = __float2bfloat16_rn(v.y - __bfloat162float(h1));
            __nv_bfloat16 l2 = __float2bfloat16_rn(v.z - __bfloat162float(h2));
            __nv_bfloat16 l3 = __float2bfloat16_rn(v.w - __bfloat162float(h3));
            uint2 ph = make_uint2(
                (uint32_t)__bfloat16_as_ushort(h0) | ((uint32_t)__bfloat16_as_ushort(h1) << 16),
                (uint32_t)__bfloat16_as_ushort(h2) | ((uint32_t)__bfloat16_as_ushort(h3) << 16));
            uint2 pl = make_uint2(
                (uint32_t)__bfloat16_as_ushort(l0) | ((uint32_t)__bfloat16_as_ushort(l1) << 16),
                (uint32_t)__bfloat16_as_ushort(l2) | ((uint32_t)__bfloat16_as_ushort(l3) << 16));
            *(uint2*)(sm + OFF_AHI + row * (PA * 2) + c4i * 8) = ph;
            *(uint2*)(sm + OFF_ALO + row * (PA * 2) + c4i * 8) = pl;
        }
        __syncthreads();

        float acc[6][4];
#pragma unroll
        for (int t = 0; t < 6; t++)
#pragma unroll
            for (int j = 0; j < 4; j++) acc[t][j] = 0.f;

#pragma unroll
        for (int kc = 0; kc < 8; kc++) {
            uint32_t ah[4], al[4];
            ldsm4(ah, aHiB + kc * 32);
            ldsm4(al, aLoB + kc * 32);
            uint32_t kb = kc * 16 * (PA * 2);
#pragma unroll
            for (int nt = 0; nt < 3; nt++) {
                uint32_t bh[4], bl[4];
                ldsm4t(bh, bHiB + kb + nt * 32);
                ldsm4t(bl, bLoB + kb + nt * 32);
                mma16816(acc[2 * nt],     ah, bh);
                mma16816(acc[2 * nt],     al, bh);
                mma16816(acc[2 * nt],     ah, bl);
                mma16816(acc[2 * nt + 1], ah, bh + 2);
                mma16816(acc[2 * nt + 1], al, bh + 2);
                mma16816(acc[2 * nt + 1], ah, bl + 2);
            }
        }

        int lr = lane >> 2;
        int lc = lane & 3;
        int row0 = r0g + warp * 16 + lr;
        int row1 = row0 + 8;
        bool v0 = row0 < n, v1 = row1 < n;
#pragma unroll
        for (int nt = 0; nt < 5; nt++) {       // cols 0..39 only
            int c0 = nt * 8 + lc * 2;
            if (c0 >= 40) continue;
            float b0v = __ldg(bias + c0), b1v = __ldg(bias + c0 + 1);
            float y00 = acc[nt][0] + b0v, y01 = acc[nt][1] + b1v;
            float y10 = acc[nt][2] + b0v, y11 = acc[nt][3] + b1v;
            if (v0) *(float2*)&out[(size_t)row0 * 40 + c0] = make_float2(y00, y01);
            if (v1) *(float2*)&out[(size_t)row1 * 40 + c0] = make_float2(y10, y11);
        }
    }
}

// ---------------- launcher -------------------------------------------------
extern "C" void kernel_launch(void* const* d_in, const int* in_sizes, int n_in,
                              void* d_out, int out_size)
{
    const float* x  = (const float*)d_in[0];
    const void*  ei = d_in[1];
    const float* W0 = (const float*)d_in[2];
    const float* b0 = (const float*)d_in[3];
    const float* W1 = (const float*)d_in[4];
    const float* b1 = (const float*)d_in[5];
    const float* W2 = (const float*)d_in[6];
    const float* b2 = (const float*)d_in[7];
    const float* Wl = (const float*)d_in[8];
    const float* bl = (const float*)d_in[9];
    float* out = (float*)d_out;

    int n = in_sizes[0] / HDIM;
    int E = in_sizes[1] / 2;

    float *bufA, *bufB, *sums, *bnm, *bns;
    __nv_bfloat16 *whi, *wlo;
    int* done;
    cudaGetSymbolAddress((void**)&bufA, g_bufA);
    cudaGetSymbolAddress((void**)&bufB, g_bufB);
    cudaGetSymbolAddress((void**)&sums, g_sums);
    cudaGetSymbolAddress((void**)&bnm,  g_bnm);
    cudaGetSymbolAddress((void**)&bns,  g_bns);
    cudaGetSymbolAddress((void**)&whi,  g_Whi);
    cudaGetSymbolAddress((void**)&wlo,  g_Wlo);
    cudaGetSymbolAddress((void**)&done, g_done);

    cudaFuncSetAttribute(k_gemm_mma, cudaFuncAttributeMaxDynamicSharedMemorySize, SMEM_MMA);
    cudaFuncSetAttribute(k_gemm40p,  cudaFuncAttributeMaxDynamicSharedMemorySize, SMEM_MMA);

    static cudaStream_t s2 = nullptr;
    static cudaEvent_t  evF = nullptr, evW = nullptr;
    if (s2 == nullptr) {
        cudaStreamCreateWithFlags(&s2, cudaStreamNonBlocking);
        cudaEventCreateWithFlags(&evF, cudaEventDisableTiming);
        cudaEventCreateWithFlags(&evW, cudaEventDisableTiming);
    }

    int nb = (n + 1023) >> 10;
    int ntiles = (n + 63) / 64;
    int ggrid  = ntiles < 296 ? ntiles : 296;   // 2 CTAs/SM persistent

    // CSR build (5 kernels) then layer-0 aggregation = 6th launch
    k_init<<<256, 256>>>(n);
    k_count<<<(E + 255) / 256, 256>>>(ei, E, n);
    k_scan12<<<nb, 256>>>(n);
    k_scan3<<<(n + 255) / 256, 256>>>(n);
    k_scatter<<<(E + 255) / 256, 256>>>(ei, E, n);

    cudaEventRecord(evF, 0);                    // fork point (after scatter)
    k_aggregate<<<(n * 32 + 255) / 256, 256>>>(x, bufA, n, nullptr, nullptr);

    // weight prep overlaps layer-0 aggregation on side stream
    cudaStreamWaitEvent(s2, evF, 0);
    k_wprep<<<64, 256, 0, s2>>>(W0, 0);
    k_wprep<<<64, 256, 0, s2>>>(W1, 1);
    k_wprep<<<64, 256, 0, s2>>>(W2, 2);
    k_wprep40<<<24, 256, 0, s2>>>(Wl);
    cudaEventRecord(evW, s2);
    cudaStreamWaitEvent(0, evW, 0);             // join before first GEMM

    const float* bs_[3] = { b0, b1, b2 };
    float* bufs[2] = { bufA, bufB };
    for (int l = 0; l < 3; l++) {
        float* Q = bufs[l & 1];
        if (l > 0) {
            const float* pm  = bnm + (l - 1) * 128;
            const float* psd = bns + (l - 1) * 128;
            k_aggregate<<<(n * 32 + 255) / 256, 256>>>(bufs[(l - 1) & 1], Q, n, pm, psd);
        }
        k_gemm_mma<<<ggrid, 128, SMEM_MMA>>>(Q, whi + l * 16384, wlo + l * 16384,
                                             bs_[l], sums + l * 256,
                                             sums + l * 256 + 128, n, ntiles,
                                             bnm + l * 128, bns + l * 128,
                                             done + l);
    }
    k_gemm40p<<<ggrid, 128, SMEM_MMA>>>(bufs[2 & 1], bl, out, n, ntiles,
                                        bnm + 2 * 128, bns + 2 * 128);
}